// round 11
// baseline (speedup 1.0000x reference)
#include <cuda_runtime.h>
#include <cuda_bf16.h>
#include <cuda_fp8.h>
#include <cstdint>

// ---------------------------------------------------------------------------
// FLASH / GAU block on GB300 — round 8:
//  * R7 base (3-stage pipeline, packed epilogue stores)   [404.1 us]
//  * H and QK projection GEMMs switched to FP8 e4m3 (m16n8k32):
//      - normed stored as e4m3 by the LN kernel
//      - Wh/Wqk transposed to NK layout, converted to e4m3 scaled by 16
//      - identical fragment plumbing (e4m3 k32 == f16 k16 with 2-byte granules)
//  * everything downstream stays bf16 (proven path)
// ---------------------------------------------------------------------------

#define DIMC   512
#define HIDC   1024
#define QKC    128
#define GRP    256
#define NTOK   16384            // 4 * 4096
#define NGRP   64               // 4 * 16
#define GPB    16               // groups per batch

// ------------------------- scratch (device globals) ------------------------
__device__ uint8_t       g_normed8[NTOK * DIMC];        // e4m3 normed
__device__ uint8_t       g_Whq   [2 * HIDC * DIMC];     // e4m3, NK ([n][k]), x16
__device__ uint8_t       g_Wqkq  [QKC * DIMC];          // e4m3, NK, x16
__device__ __nv_bfloat16 g_Wob   [HIDC * DIMC];
__device__ __nv_bfloat16 g_v     [NTOK * HIDC];
__device__ __nv_bfloat16 g_gate  [NTOK * HIDC];
__device__ __nv_bfloat16 g_qh    [4 * NTOK * QKC];      // quad_q, lin_q, quad_k, lin_k
__device__ __nv_bfloat16 g_lkT   [NGRP * QKC * GRP];    // lin_k transposed per group
__device__ __nv_bfloat16 g_S     [NGRP * GRP * GRP];
__device__ float         g_linkv [NGRP * QKC * HIDC];
__device__ __nv_bfloat16 g_linkvc[NGRP * QKC * HIDC];
__device__ __nv_bfloat16 g_outp  [NTOK * HIDC];

// ------------------------------ helpers ------------------------------------
__device__ __forceinline__ float silu_f(float v) {
    return v * (1.0f / (1.0f + __expf(-v)));
}

__device__ __forceinline__ uint32_t packbf(float a, float b) {
    __nv_bfloat162 h = __floats2bfloat162_rn(a, b);
    return *(uint32_t*)&h;
}

template<int FP8>
__device__ __forceinline__ void mma_any(float* c, const uint32_t* a, const uint32_t* b) {
    if constexpr (FP8) {
        asm volatile(
            "mma.sync.aligned.m16n8k32.row.col.f32.e4m3.e4m3.f32 "
            "{%0,%1,%2,%3},{%4,%5,%6,%7},{%8,%9},{%0,%1,%2,%3};\n"
            : "+f"(c[0]), "+f"(c[1]), "+f"(c[2]), "+f"(c[3])
            : "r"(a[0]), "r"(a[1]), "r"(a[2]), "r"(a[3]), "r"(b[0]), "r"(b[1]));
    } else {
        asm volatile(
            "mma.sync.aligned.m16n8k16.row.col.f32.bf16.bf16.f32 "
            "{%0,%1,%2,%3},{%4,%5,%6,%7},{%8,%9},{%0,%1,%2,%3};\n"
            : "+f"(c[0]), "+f"(c[1]), "+f"(c[2]), "+f"(c[3])
            : "r"(a[0]), "r"(a[1]), "r"(a[2]), "r"(a[3]), "r"(b[0]), "r"(b[1]));
    }
}

__device__ __forceinline__ void cp16(uint32_t dst, const void* src) {
    asm volatile("cp.async.cg.shared.global [%0], [%1], 16;\n" :: "r"(dst), "l"(src));
}
__device__ __forceinline__ void cp_commit() {
    asm volatile("cp.async.commit_group;\n" ::: "memory");
}
__device__ __forceinline__ void cp_wait1() {
    asm volatile("cp.async.wait_group 1;\n" ::: "memory");
}

__device__ __forceinline__ void ldsm4(uint32_t* r, uint32_t a) {
    asm volatile("ldmatrix.sync.aligned.m8n8.x4.shared.b16 {%0,%1,%2,%3},[%4];\n"
        : "=r"(r[0]), "=r"(r[1]), "=r"(r[2]), "=r"(r[3]) : "r"(a));
}
__device__ __forceinline__ void ldsm4t(uint32_t* r, uint32_t a) {
    asm volatile("ldmatrix.sync.aligned.m8n8.x4.trans.shared.b16 {%0,%1,%2,%3},[%4];\n"
        : "=r"(r[0]), "=r"(r[1]), "=r"(r[2]), "=r"(r[3]) : "r"(a));
}

struct EpiParams {
    const float* bias;
    const float* x;                 // final residual
    const __nv_bfloat16* gate;
    const float* gamma;
    const float* beta;
    float* out_f;
    __nv_bfloat16* out_b0;
    __nv_bfloat16* out_b1;
    __nv_bfloat16* out_b2;
    __nv_bfloat16* out_b3;
};

#define EPI_H       0
#define EPI_QK      1
#define EPI_RELU2   2
#define EPI_LINKV   4
#define EPI_COMBINE 5
#define EPI_FINAL   6

// packed epilogue: handles the (n, n+1) accumulator pair with one wide store
// EPI_H / EPI_QK accumulators carry the x16 weight scale -> undo with 1/16.
template<int EPI>
__device__ __forceinline__ void epi_store2(const EpiParams& p, int z, int m, int n,
                                           float a0, float a1) {
    if constexpr (EPI == EPI_H) {
        float v0 = silu_f(a0 * 0.0625f + p.bias[n]);
        float v1 = silu_f(a1 * 0.0625f + p.bias[n + 1]);
        uint32_t u = packbf(v0, v1);
        if (n < HIDC) *(uint32_t*)(p.out_b0 + (long)m * HIDC + n)        = u;
        else          *(uint32_t*)(p.out_b1 + (long)m * HIDC + n - HIDC) = u;
    } else if constexpr (EPI == EPI_QK) {
        float v0 = silu_f(a0 * 0.0625f + p.bias[n]);
        float v1 = silu_f(a1 * 0.0625f + p.bias[n + 1]);
        long o = (long)m * QKC + n;
        *(uint32_t*)(p.out_b0 + o) = packbf(v0 * p.gamma[n]           + p.beta[n],
                                            v1 * p.gamma[n + 1]       + p.beta[n + 1]);
        *(uint32_t*)(p.out_b1 + o) = packbf(v0 * p.gamma[QKC + n]     + p.beta[QKC + n],
                                            v1 * p.gamma[QKC + n + 1] + p.beta[QKC + n + 1]);
        *(uint32_t*)(p.out_b2 + o) = packbf(v0 * p.gamma[2 * QKC + n]     + p.beta[2 * QKC + n],
                                            v1 * p.gamma[2 * QKC + n + 1] + p.beta[2 * QKC + n + 1]);
        *(uint32_t*)(p.out_b3 + o) = packbf(v0 * p.gamma[3 * QKC + n]     + p.beta[3 * QKC + n],
                                            v1 * p.gamma[3 * QKC + n + 1] + p.beta[3 * QKC + n + 1]);
    } else if constexpr (EPI == EPI_RELU2) {
        float s0 = fmaxf(a0 * (1.0f / GRP), 0.0f); s0 *= s0;
        float s1 = fmaxf(a1 * (1.0f / GRP), 0.0f); s1 *= s1;
        if (n > m)     s0 = 0.0f;    // causal within group
        if (n + 1 > m) s1 = 0.0f;
        *(uint32_t*)(p.out_b0 + (long)z * GRP * GRP + m * GRP + n) = packbf(s0, s1);
    } else if constexpr (EPI == EPI_LINKV) {
        float2 r = make_float2(a0 * (1.0f / GRP), a1 * (1.0f / GRP));
        *(float2*)(p.out_f + (long)z * QKC * HIDC + (long)m * HIDC + n) = r;
    } else if constexpr (EPI == EPI_COMBINE) {
        long o = (long)z * GRP * HIDC + (long)m * HIDC + n;
        uint32_t gu = *(const uint32_t*)(p.gate + o);
        __nv_bfloat162 gh = *(__nv_bfloat162*)&gu;
        *(uint32_t*)(p.out_b0 + o) = packbf(__bfloat162float(gh.x) * a0,
                                            __bfloat162float(gh.y) * a1);
    } else { // EPI_FINAL
        long o = (long)m * DIMC + n;
        float2 xr = *(const float2*)(p.x + o);
        float2 r = make_float2(a0 + p.bias[n] + xr.x, a1 + p.bias[n + 1] + xr.y);
        *(float2*)(p.out_f + o) = r;
    }
}

// ---------------------------------------------------------------------------
// 3-stage pipelined GEMM with optional dual-source accumulation.
// Operates on 2-byte "granules": bf16 elements, or e4m3 byte-pairs (FP8=1).
//   C[M,N] = A[M,K1] @ B  (+ A2[M,K2] @ B2 if DUAL)      (K in granules)
//   BLAY == 0: B is [N,K] row-major (K-contiguous)   (ldb == K1)
//   BLAY == 1: B is [K,N] row-major (N-contiguous)   (ldb == N)
//   FP8: both operands e4m3, k32 mma; fragments identical in granule units.
//   CAUSALA:   trim K1 to (bm+1)*128 granules (S@V pair: S lower-triangular)
// Block tile 128x128, k-tile 32 granules, 256 threads, 8 warps 2(M)x4(N).
// ---------------------------------------------------------------------------
template<int EPI, int BLAY, int CAUSALA, int DUAL, int FP8>
__global__ __launch_bounds__(256) void gemm8(
    const __nv_bfloat16* __restrict__ A,  const __nv_bfloat16* __restrict__ B,
    long sAz, long sBz, int lda1,
    const __nv_bfloat16* __restrict__ A2, const __nv_bfloat16* __restrict__ B2,
    long sA2z, long sB2z, int lda2,
    int N, int K1, int K2, EpiParams p)
{
    constexpr int SAE = 128 * 40;                           // A stage granules
    constexpr int SBE = (BLAY == 1) ? 32 * 136 : 128 * 40;  // B stage granules
    extern __shared__ __nv_bfloat16 dsm[];

    const int z  = blockIdx.z;
    const int bm = blockIdx.y;
    const int bn = blockIdx.x;
    if constexpr (EPI == EPI_RELU2) { if (bn > bm) return; }   // fully masked tile

    const __nv_bfloat16* A1b = A  + (long)z * sAz;
    const __nv_bfloat16* B1b = B  + (long)z * sBz;
    const __nv_bfloat16* A2b = DUAL ? (A2 + (long)z * sA2z) : nullptr;
    const __nv_bfloat16* B2b = DUAL ? (B2 + (long)z * sB2z) : nullptr;

    const int t    = threadIdx.x;
    const int wid  = t >> 5;
    const int lane = t & 31;
    const int wm   = wid & 1;        // 0..1  (64 rows each)
    const int wn   = wid >> 1;       // 0..3  (32 cols each)
    const int gID  = lane >> 2;      // 0..7
    const int tg   = lane & 3;       // 0..3

    const int Keff1 = CAUSALA ? ((bm + 1) * 128 < K1 ? (bm + 1) * 128 : K1) : K1;
    const int nk1 = Keff1 >> 5;
    const int nk2 = DUAL ? (K2 >> 5) : 0;
    const int nt  = nk1 + nk2;

    const uint32_t sAu = (uint32_t)__cvta_generic_to_shared(dsm);
    const uint32_t sBu = sAu + 3 * SAE * 2;

    float acc[4][4][4];
    #pragma unroll
    for (int i = 0; i < 4; i++)
        #pragma unroll
        for (int j = 0; j < 4; j++)
            #pragma unroll
            for (int r = 0; r < 4; r++) acc[i][j][r] = 0.0f;

    // ---- stage loader (all cp.async) ----
    auto load_stage = [&](int st, int gt) {
        const __nv_bfloat16* Ab;
        const __nv_bfloat16* Bb;
        int lda, k0;
        if (!DUAL || gt < nk1) { Ab = A1b; Bb = B1b; lda = lda1; k0 = gt * 32; }
        else                   { Ab = A2b; Bb = B2b; lda = lda2; k0 = (gt - nk1) * 32; }
        {   // A tile: [128 rows, 32 granules] -> sA[st][row*40 + k]
            int r = t >> 2, c = (t & 3) * 8;
            uint32_t d = sAu + (uint32_t)(st * SAE + r * 40 + c) * 2;
            cp16(d,                Ab + (long)(bm * 128 + r)      * lda + k0 + c);
            cp16(d + 64 * 40 * 2,  Ab + (long)(bm * 128 + r + 64) * lda + k0 + c);
        }
        if (BLAY == 0) {   // B [N,K]: sB[st][n*40 + k]  (ldb == K1)
            int r = t >> 2, c = (t & 3) * 8;
            uint32_t d = sBu + (uint32_t)(st * SBE + r * 40 + c) * 2;
            cp16(d,                Bb + (long)(bn * 128 + r)      * K1 + k0 + c);
            cp16(d + 64 * 40 * 2,  Bb + (long)(bn * 128 + r + 64) * K1 + k0 + c);
        } else {           // B [K,N]: sB[st][k*136 + n]  (ldb == N)
            int r = t >> 4, c = (t & 15) * 8;
            uint32_t d = sBu + (uint32_t)(st * SBE + r * 136 + c) * 2;
            cp16(d,                 Bb + (long)(k0 + r)      * N + bn * 128 + c);
            cp16(d + 16 * 136 * 2,  Bb + (long)(k0 + r + 16) * N + bn * 128 + c);
        }
    };

    // prologue: stages 0 and 1 (all call sites have nt >= 2)
    load_stage(0, 0); cp_commit();
    load_stage(1, 1); cp_commit();

    for (int gt = 0; gt < nt; gt++) {
        if (gt + 2 < nt) load_stage((gt + 2) % 3, gt + 2);
        cp_commit();
        cp_wait1();
        __syncthreads();

        const int st = gt % 3;
        const uint32_t aB = sAu + (uint32_t)(st * SAE) * 2;
        const uint32_t bB = sBu + (uint32_t)(st * SBE) * 2;

        #pragma unroll
        for (int kk = 0; kk < 32; kk += 16) {
            uint32_t af[4][4];
            #pragma unroll
            for (int mt = 0; mt < 4; mt++) {
                uint32_t a = aB + (uint32_t)((wm * 64 + mt * 16 + (lane & 15)) * 40
                                             + kk + ((lane >> 4) * 8)) * 2;
                ldsm4(af[mt], a);
            }
            uint32_t bfr[2][4];
            #pragma unroll
            for (int h = 0; h < 2; h++) {
                int n0 = wn * 32 + h * 16;
                if (BLAY == 0) {
                    uint32_t a = bB + (uint32_t)((n0 + (lane & 7) + ((lane >> 4) << 3)) * 40
                                                 + kk + (((lane >> 3) & 1) * 8)) * 2;
                    ldsm4(bfr[h], a);
                } else {
                    uint32_t a = bB + (uint32_t)((kk + (lane & 15)) * 136
                                                 + n0 + ((lane >> 4) * 8)) * 2;
                    ldsm4t(bfr[h], a);
                }
            }
            #pragma unroll
            for (int mt = 0; mt < 4; mt++)
                #pragma unroll
                for (int j = 0; j < 4; j++) {
                    uint32_t bb[2] = { bfr[j >> 1][(j & 1) * 2],
                                       bfr[j >> 1][(j & 1) * 2 + 1] };
                    mma_any<FP8>(acc[mt][j], af[mt], bb);
                }
        }
        __syncthreads();
    }

    #pragma unroll
    for (int mt = 0; mt < 4; mt++)
        #pragma unroll
        for (int j = 0; j < 4; j++) {
            int m0 = bm * 128 + wm * 64 + mt * 16 + gID;
            int n0 = bn * 128 + wn * 32 + j * 8 + tg * 2;
            epi_store2<EPI>(p, z, m0,     n0, acc[mt][j][0], acc[mt][j][1]);
            epi_store2<EPI>(p, z, m0 + 8, n0, acc[mt][j][2], acc[mt][j][3]);
        }
}

// ----------------------------- small kernels --------------------------------
// Wo fp32 -> bf16 (KN layout unchanged)
__global__ void f2b_wo(const float* __restrict__ Wo, __nv_bfloat16* __restrict__ Wob) {
    int i = blockIdx.x * 256 + threadIdx.x;
    if (i < HIDC * DIMC) Wob[i] = __float2bfloat16(Wo[i]);
}

// transpose-convert: in [K][N] fp32 -> out [N][K] e4m3 scaled x16
__global__ void wtrans_q(const float* __restrict__ in, uint8_t* __restrict__ out,
                         int K, int N) {
    __shared__ float s[32][33];
    int n0 = blockIdx.x * 32, k0 = blockIdx.y * 32;
    int tx = threadIdx.x, ty = threadIdx.y;   // 32 x 8
    #pragma unroll
    for (int i = 0; i < 4; i++) {
        int r = ty + i * 8;
        s[r][tx] = in[(long)(k0 + r) * N + n0 + tx];
    }
    __syncthreads();
    #pragma unroll
    for (int i = 0; i < 4; i++) {
        int r = ty + i * 8;
        float v = s[tx][r] * 16.0f;
        out[(long)(n0 + r) * K + k0 + tx] =
            (uint8_t)__nv_cvt_float_to_fp8(v, __NV_SATFINITE, __NV_E4M3);
    }
}

// LayerNorm: 128 threads, float4 loads, packed e4m3 x4 stores
__global__ void ln_kernel(const float4* __restrict__ x4, const float4* __restrict__ w4,
                          const float4* __restrict__ b4, uint32_t* __restrict__ out) {
    int tok = blockIdx.x;
    int t = threadIdx.x;
    float4 v = x4[(long)tok * 128 + t];
    float s  = v.x + v.y + v.z + v.w;
    float sq = v.x * v.x + v.y * v.y + v.z * v.z + v.w * v.w;
    #pragma unroll
    for (int o = 16; o; o >>= 1) {
        s  += __shfl_xor_sync(0xffffffffu, s,  o);
        sq += __shfl_xor_sync(0xffffffffu, sq, o);
    }
    __shared__ float ss[4], sv[4];
    if ((t & 31) == 0) { ss[t >> 5] = s; sv[t >> 5] = sq; }
    __syncthreads();
    float S = ss[0] + ss[1] + ss[2] + ss[3];
    float Q = sv[0] + sv[1] + sv[2] + sv[3];
    float mu  = S * (1.0f / DIMC);
    float var = Q * (1.0f / DIMC) - mu * mu;
    float rs  = rsqrtf(var + 1e-5f);
    float4 w = w4[t], b = b4[t];
    float r0 = (v.x - mu) * rs * w.x + b.x;
    float r1 = (v.y - mu) * rs * w.y + b.y;
    float r2 = (v.z - mu) * rs * w.z + b.z;
    float r3 = (v.w - mu) * rs * w.w + b.w;
    uint32_t u = (uint32_t)__nv_cvt_float_to_fp8(r0, __NV_SATFINITE, __NV_E4M3)
               | ((uint32_t)__nv_cvt_float_to_fp8(r1, __NV_SATFINITE, __NV_E4M3) << 8)
               | ((uint32_t)__nv_cvt_float_to_fp8(r2, __NV_SATFINITE, __NV_E4M3) << 16)
               | ((uint32_t)__nv_cvt_float_to_fp8(r3, __NV_SATFINITE, __NV_E4M3) << 24);
    out[(long)tok * 128 + t] = u;
}

// lkT[z][d][t] = lk[z*256 + t][d]
__global__ void transpose_lk(const __nv_bfloat16* __restrict__ lk, __nv_bfloat16* __restrict__ lkT) {
    __shared__ __nv_bfloat16 s[32][33];
    int z = blockIdx.z, tT = blockIdx.x, dT = blockIdx.y;
    int tx = threadIdx.x, ty = threadIdx.y;   // 32 x 8
    #pragma unroll
    for (int i = 0; i < 4; i++) {
        int r = ty + i * 8;
        s[r][tx] = lk[(long)(z * GRP + tT * 32 + r) * QKC + dT * 32 + tx];
    }
    __syncthreads();
    #pragma unroll
    for (int i = 0; i < 4; i++) {
        int r = ty + i * 8;
        lkT[(long)z * QKC * GRP + (long)(dT * 32 + r) * GRP + tT * 32 + tx] = s[tx][r];
    }
}

// exclusive cumsum over groups (g dim), fp32 in -> bf16 out
__global__ void cumsum_kv(const float* __restrict__ kv, __nv_bfloat16* __restrict__ out) {
    long i = (long)blockIdx.x * 256 + threadIdx.x;
    const long GE = (long)QKC * HIDC;                 // 131072
    if (i >= 4 * GE) return;
    int  bb = (int)(i / GE);
    long e  = i % GE;
    float s = 0.0f;
    #pragma unroll
    for (int g = 0; g < GPB; g++) {
        long o = ((long)(bb * GPB + g)) * GE + e;
        out[o] = __float2bfloat16(s);
        s += kv[o];
    }
}

// ------------------------------- launcher -----------------------------------
extern "C" void kernel_launch(void* const* d_in, const int* in_sizes, int n_in,
                              void* d_out, int out_size) {
    const float* x     = (const float*)d_in[0];
    const float* ln_w  = (const float*)d_in[1];
    const float* ln_b  = (const float*)d_in[2];
    const float* Wh    = (const float*)d_in[3];
    const float* bh    = (const float*)d_in[4];
    const float* Wqk   = (const float*)d_in[5];
    const float* bqk   = (const float*)d_in[6];
    const float* gamma = (const float*)d_in[7];
    const float* beta  = (const float*)d_in[8];
    const float* Wo    = (const float*)d_in[9];
    const float* bo    = (const float*)d_in[10];
    float* out = (float*)d_out;

    uint8_t *normed8, *Whq, *Wqkq;
    __nv_bfloat16 *Wob, *v, *gate, *qh, *lkT, *S, *linkvc, *outp;
    float *linkv;
    cudaGetSymbolAddress((void**)&normed8, g_normed8);
    cudaGetSymbolAddress((void**)&Whq,    g_Whq);
    cudaGetSymbolAddress((void**)&Wqkq,   g_Wqkq);
    cudaGetSymbolAddress((void**)&Wob,    g_Wob);
    cudaGetSymbolAddress((void**)&v,      g_v);
    cudaGetSymbolAddress((void**)&gate,   g_gate);
    cudaGetSymbolAddress((void**)&qh,     g_qh);
    cudaGetSymbolAddress((void**)&lkT,    g_lkT);
    cudaGetSymbolAddress((void**)&S,      g_S);
    cudaGetSymbolAddress((void**)&linkv,  g_linkv);
    cudaGetSymbolAddress((void**)&linkvc, g_linkvc);
    cudaGetSymbolAddress((void**)&outp,   g_outp);

    const long HSZ = (long)NTOK * QKC;   // per-head size
    __nv_bfloat16* quad_q = qh;
    __nv_bfloat16* lin_q  = qh + HSZ;
    __nv_bfloat16* quad_k = qh + 2 * HSZ;
    __nv_bfloat16* lin_k  = qh + 3 * HSZ;

    // granule views for the fp8 GEMMs (granule = 2 bytes = 2 x e4m3)
    const int KG = DIMC / 2;             // 256 granules of K
    const __nv_bfloat16* normedG = (const __nv_bfloat16*)normed8;
    const __nv_bfloat16* WhqG    = (const __nv_bfloat16*)Whq;
    const __nv_bfloat16* WqkqG   = (const __nv_bfloat16*)Wqkq;

    // dynamic smem sizes (3 stages)
    const int SM1 = 3 * (128 * 40 + 32 * 136) * 2;   // 56832
    const int SM0 = 3 * (128 * 40 + 128 * 40) * 2;   // 61440
    cudaFuncSetAttribute((const void*)gemm8<EPI_H,       0, 0, 0, 1>, cudaFuncAttributeMaxDynamicSharedMemorySize, SM0);
    cudaFuncSetAttribute((const void*)gemm8<EPI_QK,      0, 0, 0, 1>, cudaFuncAttributeMaxDynamicSharedMemorySize, SM0);
    cudaFuncSetAttribute((const void*)gemm8<EPI_RELU2,   0, 0, 0, 0>, cudaFuncAttributeMaxDynamicSharedMemorySize, SM0);
    cudaFuncSetAttribute((const void*)gemm8<EPI_LINKV,   1, 0, 0, 0>, cudaFuncAttributeMaxDynamicSharedMemorySize, SM1);
    cudaFuncSetAttribute((const void*)gemm8<EPI_COMBINE, 1, 1, 1, 0>, cudaFuncAttributeMaxDynamicSharedMemorySize, SM1);
    cudaFuncSetAttribute((const void*)gemm8<EPI_FINAL,   1, 0, 0, 0>, cudaFuncAttributeMaxDynamicSharedMemorySize, SM1);

    // 1. weight converts + layernorm
    f2b_wo<<<(HIDC * DIMC + 255) / 256, 256>>>(Wo, Wob);
    wtrans_q<<<dim3(2 * HIDC / 32, DIMC / 32), dim3(32, 8)>>>(Wh,  Whq,  DIMC, 2 * HIDC);
    wtrans_q<<<dim3(QKC / 32,      DIMC / 32), dim3(32, 8)>>>(Wqk, Wqkq, DIMC, QKC);
    ln_kernel<<<NTOK, 128>>>((const float4*)x, (const float4*)ln_w,
                             (const float4*)ln_b, (uint32_t*)normed8);

    // 2. h = silu(normed @ Wh + bh) -> v, gate     [FP8]
    {
        EpiParams p{}; p.bias = bh; p.out_b0 = v; p.out_b1 = gate;
        gemm8<EPI_H, 0, 0, 0, 1><<<dim3(2 * HIDC / 128, NTOK / 128, 1), 256, SM0>>>(
            normedG, WhqG, 0, 0, KG, nullptr, nullptr, 0, 0, 0,
            2 * HIDC, KG, 0, p);
    }
    // 3. qk heads                                  [FP8]
    {
        EpiParams p{}; p.bias = bqk; p.gamma = gamma; p.beta = beta;
        p.out_b0 = quad_q; p.out_b1 = lin_q; p.out_b2 = quad_k; p.out_b3 = lin_k;
        gemm8<EPI_QK, 0, 0, 0, 1><<<dim3(1, NTOK / 128, 1), 256, SM0>>>(
            normedG, WqkqG, 0, 0, KG, nullptr, nullptr, 0, 0, 0,
            QKC, KG, 0, p);
    }
    // lk^T per group
    transpose_lk<<<dim3(GRP / 32, QKC / 32, NGRP), dim3(32, 8)>>>(lin_k, lkT);

    // 4. S = relu2(QK^T / G), causal (upper block skipped)
    {
        EpiParams p{}; p.out_b0 = S;
        gemm8<EPI_RELU2, 0, 0, 0, 0><<<dim3(2, 2, NGRP), 256, SM0>>>(
            quad_q, quad_k, (long)GRP * QKC, (long)GRP * QKC, QKC,
            nullptr, nullptr, 0, 0, 0, GRP, QKC, 0, p);
    }
    // 6. linkv = lk^T @ V / G
    {
        EpiParams p{}; p.out_f = linkv;
        gemm8<EPI_LINKV, 1, 0, 0, 0><<<dim3(HIDC / 128, 1, NGRP), 256, SM1>>>(
            lkT, v, (long)QKC * GRP, (long)GRP * HIDC, GRP,
            nullptr, nullptr, 0, 0, 0, HIDC, GRP, 0, p);
    }
    // 7. exclusive cumsum over groups
    cumsum_kv<<<(4 * QKC * HIDC / 256), 256>>>(linkv, linkvc);

    // 8. outp = gate * (S@V + lq @ linkvc)    [fused quad + combine]
    {
        EpiParams p{}; p.gate = gate; p.out_b0 = outp;
        gemm8<EPI_COMBINE, 1, 1, 1, 0><<<dim3(HIDC / 128, 2, NGRP), 256, SM1>>>(
            S, v, (long)GRP * GRP, (long)GRP * HIDC, GRP,
            lin_q, linkvc, (long)GRP * QKC, (long)QKC * HIDC, QKC,
            HIDC, GRP, QKC, p);
    }
    // 9. out = outp @ Wo + bo + x
    {
        EpiParams p{}; p.bias = bo; p.x = x; p.out_f = out;
        gemm8<EPI_FINAL, 1, 0, 0, 0><<<dim3(DIMC / 128, NTOK / 128, 1), 256, SM1>>>(
            outp, Wob, 0, 0, HIDC, nullptr, nullptr, 0, 0, 0,
            DIMC, HIDC, 0, p);
    }
}

// round 12
// speedup vs baseline: 1.1305x; 1.1305x over previous
#include <cuda_runtime.h>
#include <cuda_bf16.h>
#include <cstdint>

// ---------------------------------------------------------------------------
// FLASH / GAU block on GB300 — round 11:
//  * R7 base (bf16 everywhere, 3-stage pipeline, packed epilogue stores)
//  * FP8 reverted (mma.sync e4m3 is de-rated on sm_103a — measured regression)
//  * QK projection re-fused into H GEMM (N=2176) now that stores are packed
// ---------------------------------------------------------------------------

#define DIMC   512
#define HIDC   1024
#define QKC    128
#define GRP    256
#define NTOK   16384            // 4 * 4096
#define NGRP   64               // 4 * 16
#define GPB    16               // groups per batch
#define NHQ    (2 * HIDC + QKC) // 2176  (fused H+QK output width)

// ------------------------- scratch (device globals) ------------------------
__device__ __nv_bfloat16 g_normed[NTOK * DIMC];
__device__ __nv_bfloat16 g_Wc    [DIMC * NHQ];          // [Wh | Wqk] fused, KN
__device__ __nv_bfloat16 g_Wob   [HIDC * DIMC];
__device__ __nv_bfloat16 g_v     [NTOK * HIDC];
__device__ __nv_bfloat16 g_gate  [NTOK * HIDC];
__device__ __nv_bfloat16 g_qh    [4 * NTOK * QKC];      // quad_q, lin_q, quad_k, lin_k
__device__ __nv_bfloat16 g_lkT   [NGRP * QKC * GRP];    // lin_k transposed per group
__device__ __nv_bfloat16 g_S     [NGRP * GRP * GRP];
__device__ float         g_linkv [NGRP * QKC * HIDC];
__device__ __nv_bfloat16 g_linkvc[NGRP * QKC * HIDC];
__device__ __nv_bfloat16 g_outp  [NTOK * HIDC];

// ------------------------------ helpers ------------------------------------
__device__ __forceinline__ float silu_f(float v) {
    return v * (1.0f / (1.0f + __expf(-v)));
}

__device__ __forceinline__ uint32_t packbf(float a, float b) {
    __nv_bfloat162 h = __floats2bfloat162_rn(a, b);
    return *(uint32_t*)&h;
}

__device__ __forceinline__ void mma16816(float* c, const uint32_t* a, const uint32_t* b) {
    asm volatile(
        "mma.sync.aligned.m16n8k16.row.col.f32.bf16.bf16.f32 "
        "{%0,%1,%2,%3},{%4,%5,%6,%7},{%8,%9},{%0,%1,%2,%3};\n"
        : "+f"(c[0]), "+f"(c[1]), "+f"(c[2]), "+f"(c[3])
        : "r"(a[0]), "r"(a[1]), "r"(a[2]), "r"(a[3]), "r"(b[0]), "r"(b[1]));
}

__device__ __forceinline__ void cp16(uint32_t dst, const void* src) {
    asm volatile("cp.async.cg.shared.global [%0], [%1], 16;\n" :: "r"(dst), "l"(src));
}
__device__ __forceinline__ void cp_commit() {
    asm volatile("cp.async.commit_group;\n" ::: "memory");
}
__device__ __forceinline__ void cp_wait1() {
    asm volatile("cp.async.wait_group 1;\n" ::: "memory");
}

__device__ __forceinline__ void ldsm4(uint32_t* r, uint32_t a) {
    asm volatile("ldmatrix.sync.aligned.m8n8.x4.shared.b16 {%0,%1,%2,%3},[%4];\n"
        : "=r"(r[0]), "=r"(r[1]), "=r"(r[2]), "=r"(r[3]) : "r"(a));
}
__device__ __forceinline__ void ldsm4t(uint32_t* r, uint32_t a) {
    asm volatile("ldmatrix.sync.aligned.m8n8.x4.trans.shared.b16 {%0,%1,%2,%3},[%4];\n"
        : "=r"(r[0]), "=r"(r[1]), "=r"(r[2]), "=r"(r[3]) : "r"(a));
}

struct EpiParams {
    const float* bias;              // bh / bo
    const float* bias2;             // bqk (HQK) or residual x (final)
    const __nv_bfloat16* gate;
    const float* gamma;
    const float* beta;
    float* out_f;
    __nv_bfloat16* out_b0;
    __nv_bfloat16* out_b1;
    __nv_bfloat16* out_b2;
    __nv_bfloat16* out_b3;
    __nv_bfloat16* out_b4;
    __nv_bfloat16* out_b5;
};

#define EPI_HQK     0
#define EPI_RELU2   2
#define EPI_LINKV   4
#define EPI_COMBINE 5
#define EPI_FINAL   6

// packed epilogue: handles the (n, n+1) accumulator pair with wide stores
template<int EPI>
__device__ __forceinline__ void epi_store2(const EpiParams& p, int z, int m, int n,
                                           float a0, float a1) {
    if constexpr (EPI == EPI_HQK) {
        if (n < 2 * HIDC) {
            float v0 = silu_f(a0 + p.bias[n]);
            float v1 = silu_f(a1 + p.bias[n + 1]);
            uint32_t u = packbf(v0, v1);
            if (n < HIDC) *(uint32_t*)(p.out_b0 + (long)m * HIDC + n)        = u;
            else          *(uint32_t*)(p.out_b1 + (long)m * HIDC + n - HIDC) = u;
        } else {
            int nq = n - 2 * HIDC;
            float v0 = silu_f(a0 + p.bias2[nq]);
            float v1 = silu_f(a1 + p.bias2[nq + 1]);
            long o = (long)m * QKC + nq;
            *(uint32_t*)(p.out_b2 + o) = packbf(v0 * p.gamma[nq]         + p.beta[nq],
                                                v1 * p.gamma[nq + 1]     + p.beta[nq + 1]);
            *(uint32_t*)(p.out_b3 + o) = packbf(v0 * p.gamma[QKC + nq]   + p.beta[QKC + nq],
                                                v1 * p.gamma[QKC + nq + 1] + p.beta[QKC + nq + 1]);
            *(uint32_t*)(p.out_b4 + o) = packbf(v0 * p.gamma[2 * QKC + nq]     + p.beta[2 * QKC + nq],
                                                v1 * p.gamma[2 * QKC + nq + 1] + p.beta[2 * QKC + nq + 1]);
            *(uint32_t*)(p.out_b5 + o) = packbf(v0 * p.gamma[3 * QKC + nq]     + p.beta[3 * QKC + nq],
                                                v1 * p.gamma[3 * QKC + nq + 1] + p.beta[3 * QKC + nq + 1]);
        }
    } else if constexpr (EPI == EPI_RELU2) {
        float s0 = fmaxf(a0 * (1.0f / GRP), 0.0f); s0 *= s0;
        float s1 = fmaxf(a1 * (1.0f / GRP), 0.0f); s1 *= s1;
        if (n > m)     s0 = 0.0f;    // causal within group
        if (n + 1 > m) s1 = 0.0f;
        *(uint32_t*)(p.out_b0 + (long)z * GRP * GRP + m * GRP + n) = packbf(s0, s1);
    } else if constexpr (EPI == EPI_LINKV) {
        float2 r = make_float2(a0 * (1.0f / GRP), a1 * (1.0f / GRP));
        *(float2*)(p.out_f + (long)z * QKC * HIDC + (long)m * HIDC + n) = r;
    } else if constexpr (EPI == EPI_COMBINE) {
        long o = (long)z * GRP * HIDC + (long)m * HIDC + n;
        uint32_t gu = *(const uint32_t*)(p.gate + o);
        __nv_bfloat162 gh = *(__nv_bfloat162*)&gu;
        *(uint32_t*)(p.out_b0 + o) = packbf(__bfloat162float(gh.x) * a0,
                                            __bfloat162float(gh.y) * a1);
    } else { // EPI_FINAL
        long o = (long)m * DIMC + n;
        float2 xr = *(const float2*)(p.bias2 + o);
        float2 r = make_float2(a0 + p.bias[n] + xr.x, a1 + p.bias[n + 1] + xr.y);
        *(float2*)(p.out_f + o) = r;
    }
}

// ---------------------------------------------------------------------------
// 3-stage pipelined bf16 GEMM with optional dual-source accumulation.
//   C[M,N] = A[M,K1] @ B  (+ A2[M,K2] @ B2 if DUAL)
//   BLAY == 0: B is [N,K] row-major (K-contiguous)   (ldb == K1)
//   BLAY == 1: B is [K,N] row-major (N-contiguous)   (ldb == N)
//   CAUSALA:   trim K1 to (bm+1)*128 (S@V pair: S lower-triangular)
// Block tile 128x128, k-tile 32, 256 threads, 8 warps 2(M)x4(N), warp 64x32.
// ---------------------------------------------------------------------------
template<int EPI, int BLAY, int CAUSALA, int DUAL>
__global__ __launch_bounds__(256) void gemm11(
    const __nv_bfloat16* __restrict__ A,  const __nv_bfloat16* __restrict__ B,
    long sAz, long sBz, int lda1,
    const __nv_bfloat16* __restrict__ A2, const __nv_bfloat16* __restrict__ B2,
    long sA2z, long sB2z, int lda2,
    int N, int K1, int K2, EpiParams p)
{
    constexpr int SAE = 128 * 40;                           // A stage elems
    constexpr int SBE = (BLAY == 1) ? 32 * 136 : 128 * 40;  // B stage elems
    extern __shared__ __nv_bfloat16 dsm[];

    const int z  = blockIdx.z;
    const int bm = blockIdx.y;
    const int bn = blockIdx.x;
    if constexpr (EPI == EPI_RELU2) { if (bn > bm) return; }   // fully masked tile

    const __nv_bfloat16* A1b = A  + (long)z * sAz;
    const __nv_bfloat16* B1b = B  + (long)z * sBz;
    const __nv_bfloat16* A2b = DUAL ? (A2 + (long)z * sA2z) : nullptr;
    const __nv_bfloat16* B2b = DUAL ? (B2 + (long)z * sB2z) : nullptr;

    const int t    = threadIdx.x;
    const int wid  = t >> 5;
    const int lane = t & 31;
    const int wm   = wid & 1;        // 0..1  (64 rows each)
    const int wn   = wid >> 1;       // 0..3  (32 cols each)
    const int gID  = lane >> 2;      // 0..7
    const int tg   = lane & 3;       // 0..3

    const int Keff1 = CAUSALA ? ((bm + 1) * 128 < K1 ? (bm + 1) * 128 : K1) : K1;
    const int nk1 = Keff1 >> 5;
    const int nk2 = DUAL ? (K2 >> 5) : 0;
    const int nt  = nk1 + nk2;

    const uint32_t sAu = (uint32_t)__cvta_generic_to_shared(dsm);
    const uint32_t sBu = sAu + 3 * SAE * 2;

    float acc[4][4][4];
    #pragma unroll
    for (int i = 0; i < 4; i++)
        #pragma unroll
        for (int j = 0; j < 4; j++)
            #pragma unroll
            for (int r = 0; r < 4; r++) acc[i][j][r] = 0.0f;

    // ---- stage loader (all cp.async) ----
    auto load_stage = [&](int st, int gt) {
        const __nv_bfloat16* Ab;
        const __nv_bfloat16* Bb;
        int lda, k0;
        if (!DUAL || gt < nk1) { Ab = A1b; Bb = B1b; lda = lda1; k0 = gt * 32; }
        else                   { Ab = A2b; Bb = B2b; lda = lda2; k0 = (gt - nk1) * 32; }
        {   // A tile: [128 rows, 32 k] -> sA[st][row*40 + k]
            int r = t >> 2, c = (t & 3) * 8;
            uint32_t d = sAu + (uint32_t)(st * SAE + r * 40 + c) * 2;
            cp16(d,                Ab + (long)(bm * 128 + r)      * lda + k0 + c);
            cp16(d + 64 * 40 * 2,  Ab + (long)(bm * 128 + r + 64) * lda + k0 + c);
        }
        if (BLAY == 0) {   // B [N,K]: sB[st][n*40 + k]  (ldb == K1)
            int r = t >> 2, c = (t & 3) * 8;
            uint32_t d = sBu + (uint32_t)(st * SBE + r * 40 + c) * 2;
            cp16(d,                Bb + (long)(bn * 128 + r)      * K1 + k0 + c);
            cp16(d + 64 * 40 * 2,  Bb + (long)(bn * 128 + r + 64) * K1 + k0 + c);
        } else {           // B [K,N]: sB[st][k*136 + n]  (ldb == N)
            int r = t >> 4, c = (t & 15) * 8;
            uint32_t d = sBu + (uint32_t)(st * SBE + r * 136 + c) * 2;
            cp16(d,                 Bb + (long)(k0 + r)      * N + bn * 128 + c);
            cp16(d + 16 * 136 * 2,  Bb + (long)(k0 + r + 16) * N + bn * 128 + c);
        }
    };

    // prologue: stages 0 and 1 (all call sites have nt >= 2)
    load_stage(0, 0); cp_commit();
    load_stage(1, 1); cp_commit();

    for (int gt = 0; gt < nt; gt++) {
        if (gt + 2 < nt) load_stage((gt + 2) % 3, gt + 2);
        cp_commit();
        cp_wait1();
        __syncthreads();

        const int st = gt % 3;
        const uint32_t aB = sAu + (uint32_t)(st * SAE) * 2;
        const uint32_t bB = sBu + (uint32_t)(st * SBE) * 2;

        #pragma unroll
        for (int kk = 0; kk < 32; kk += 16) {
            uint32_t af[4][4];
            #pragma unroll
            for (int mt = 0; mt < 4; mt++) {
                uint32_t a = aB + (uint32_t)((wm * 64 + mt * 16 + (lane & 15)) * 40
                                             + kk + ((lane >> 4) * 8)) * 2;
                ldsm4(af[mt], a);
            }
            uint32_t bfr[2][4];
            #pragma unroll
            for (int h = 0; h < 2; h++) {
                int n0 = wn * 32 + h * 16;
                if (BLAY == 0) {
                    uint32_t a = bB + (uint32_t)((n0 + (lane & 7) + ((lane >> 4) << 3)) * 40
                                                 + kk + (((lane >> 3) & 1) * 8)) * 2;
                    ldsm4(bfr[h], a);
                } else {
                    uint32_t a = bB + (uint32_t)((kk + (lane & 15)) * 136
                                                 + n0 + ((lane >> 4) * 8)) * 2;
                    ldsm4t(bfr[h], a);
                }
            }
            #pragma unroll
            for (int mt = 0; mt < 4; mt++)
                #pragma unroll
                for (int j = 0; j < 4; j++) {
                    uint32_t bb[2] = { bfr[j >> 1][(j & 1) * 2],
                                       bfr[j >> 1][(j & 1) * 2 + 1] };
                    mma16816(acc[mt][j], af[mt], bb);
                }
        }
        __syncthreads();
    }

    #pragma unroll
    for (int mt = 0; mt < 4; mt++)
        #pragma unroll
        for (int j = 0; j < 4; j++) {
            int m0 = bm * 128 + wm * 64 + mt * 16 + gID;
            int n0 = bn * 128 + wn * 32 + j * 8 + tg * 2;
            epi_store2<EPI>(p, z, m0,     n0, acc[mt][j][0], acc[mt][j][1]);
            epi_store2<EPI>(p, z, m0 + 8, n0, acc[mt][j][2], acc[mt][j][3]);
        }
}

// ----------------------------- small kernels --------------------------------
// converts Wh+Wqk into the fused [512 x 2176] KN matrix, and Wo -> bf16
__global__ void f2b_all(const float* __restrict__ Wh, const float* __restrict__ Wqk,
                        const float* __restrict__ Wo,
                        __nv_bfloat16* __restrict__ Wc, __nv_bfloat16* __restrict__ Wob) {
    const int N1 = DIMC * 2 * HIDC;          // 1048576
    const int N2 = DIMC * QKC;               // 65536
    const int N3 = HIDC * DIMC;              // 524288
    int i = blockIdx.x * 256 + threadIdx.x;
    if (i < N1) {
        int k = i / (2 * HIDC), j = i % (2 * HIDC);
        Wc[(long)k * NHQ + j] = __float2bfloat16(Wh[i]);
    } else if (i < N1 + N2) {
        int e = i - N1;
        int k = e / QKC, j = e % QKC;
        Wc[(long)k * NHQ + 2 * HIDC + j] = __float2bfloat16(Wqk[e]);
    } else if (i < N1 + N2 + N3) {
        Wob[i - N1 - N2] = __float2bfloat16(Wo[i - N1 - N2]);
    }
}

// 128 threads, float4 loads, bf16x2 packed stores
__global__ void ln_kernel(const float4* __restrict__ x4, const float4* __restrict__ w4,
                          const float4* __restrict__ b4, uint2* __restrict__ out) {
    int tok = blockIdx.x;
    int t = threadIdx.x;
    float4 v = x4[(long)tok * 128 + t];
    float s  = v.x + v.y + v.z + v.w;
    float sq = v.x * v.x + v.y * v.y + v.z * v.z + v.w * v.w;
    #pragma unroll
    for (int o = 16; o; o >>= 1) {
        s  += __shfl_xor_sync(0xffffffffu, s,  o);
        sq += __shfl_xor_sync(0xffffffffu, sq, o);
    }
    __shared__ float ss[4], sv[4];
    if ((t & 31) == 0) { ss[t >> 5] = s; sv[t >> 5] = sq; }
    __syncthreads();
    float S = ss[0] + ss[1] + ss[2] + ss[3];
    float Q = sv[0] + sv[1] + sv[2] + sv[3];
    float mu  = S * (1.0f / DIMC);
    float var = Q * (1.0f / DIMC) - mu * mu;
    float rs  = rsqrtf(var + 1e-5f);
    float4 w = w4[t], b = b4[t];
    float r0 = (v.x - mu) * rs * w.x + b.x;
    float r1 = (v.y - mu) * rs * w.y + b.y;
    float r2 = (v.z - mu) * rs * w.z + b.z;
    float r3 = (v.w - mu) * rs * w.w + b.w;
    uint2 u;
    u.x = packbf(r0, r1);
    u.y = packbf(r2, r3);
    out[(long)tok * 128 + t] = u;
}

// lkT[z][d][t] = lk[z*256 + t][d]
__global__ void transpose_lk(const __nv_bfloat16* __restrict__ lk, __nv_bfloat16* __restrict__ lkT) {
    __shared__ __nv_bfloat16 s[32][33];
    int z = blockIdx.z, tT = blockIdx.x, dT = blockIdx.y;
    int tx = threadIdx.x, ty = threadIdx.y;   // 32 x 8
    #pragma unroll
    for (int i = 0; i < 4; i++) {
        int r = ty + i * 8;
        s[r][tx] = lk[(long)(z * GRP + tT * 32 + r) * QKC + dT * 32 + tx];
    }
    __syncthreads();
    #pragma unroll
    for (int i = 0; i < 4; i++) {
        int r = ty + i * 8;
        lkT[(long)z * QKC * GRP + (long)(dT * 32 + r) * GRP + tT * 32 + tx] = s[tx][r];
    }
}

// exclusive cumsum over groups (g dim), fp32 in -> bf16 out
__global__ void cumsum_kv(const float* __restrict__ kv, __nv_bfloat16* __restrict__ out) {
    long i = (long)blockIdx.x * 256 + threadIdx.x;
    const long GE = (long)QKC * HIDC;                 // 131072
    if (i >= 4 * GE) return;
    int  bb = (int)(i / GE);
    long e  = i % GE;
    float s = 0.0f;
    #pragma unroll
    for (int g = 0; g < GPB; g++) {
        long o = ((long)(bb * GPB + g)) * GE + e;
        out[o] = __float2bfloat16(s);
        s += kv[o];
    }
}

// ------------------------------- launcher -----------------------------------
extern "C" void kernel_launch(void* const* d_in, const int* in_sizes, int n_in,
                              void* d_out, int out_size) {
    const float* x     = (const float*)d_in[0];
    const float* ln_w  = (const float*)d_in[1];
    const float* ln_b  = (const float*)d_in[2];
    const float* Wh    = (const float*)d_in[3];
    const float* bh    = (const float*)d_in[4];
    const float* Wqk   = (const float*)d_in[5];
    const float* bqk   = (const float*)d_in[6];
    const float* gamma = (const float*)d_in[7];
    const float* beta  = (const float*)d_in[8];
    const float* Wo    = (const float*)d_in[9];
    const float* bo    = (const float*)d_in[10];
    float* out = (float*)d_out;

    __nv_bfloat16 *normed, *Wc, *Wob, *v, *gate, *qh, *lkT, *S, *linkvc, *outp;
    float *linkv;
    cudaGetSymbolAddress((void**)&normed, g_normed);
    cudaGetSymbolAddress((void**)&Wc,     g_Wc);
    cudaGetSymbolAddress((void**)&Wob,    g_Wob);
    cudaGetSymbolAddress((void**)&v,      g_v);
    cudaGetSymbolAddress((void**)&gate,   g_gate);
    cudaGetSymbolAddress((void**)&qh,     g_qh);
    cudaGetSymbolAddress((void**)&lkT,    g_lkT);
    cudaGetSymbolAddress((void**)&S,      g_S);
    cudaGetSymbolAddress((void**)&linkv,  g_linkv);
    cudaGetSymbolAddress((void**)&linkvc, g_linkvc);
    cudaGetSymbolAddress((void**)&outp,   g_outp);

    const long HSZ = (long)NTOK * QKC;   // per-head size
    __nv_bfloat16* quad_q = qh;
    __nv_bfloat16* lin_q  = qh + HSZ;
    __nv_bfloat16* quad_k = qh + 2 * HSZ;
    __nv_bfloat16* lin_k  = qh + 3 * HSZ;

    // dynamic smem sizes (3 stages)
    const int SM1 = 3 * (128 * 40 + 32 * 136) * 2;   // 56832
    const int SM0 = 3 * (128 * 40 + 128 * 40) * 2;   // 61440
    cudaFuncSetAttribute((const void*)gemm11<EPI_HQK,     1, 0, 0>, cudaFuncAttributeMaxDynamicSharedMemorySize, SM1);
    cudaFuncSetAttribute((const void*)gemm11<EPI_RELU2,   0, 0, 0>, cudaFuncAttributeMaxDynamicSharedMemorySize, SM0);
    cudaFuncSetAttribute((const void*)gemm11<EPI_LINKV,   1, 0, 0>, cudaFuncAttributeMaxDynamicSharedMemorySize, SM1);
    cudaFuncSetAttribute((const void*)gemm11<EPI_COMBINE, 1, 1, 1>, cudaFuncAttributeMaxDynamicSharedMemorySize, SM1);
    cudaFuncSetAttribute((const void*)gemm11<EPI_FINAL,   1, 0, 0>, cudaFuncAttributeMaxDynamicSharedMemorySize, SM1);

    // 1. weight converts + layernorm
    const int NCV = DIMC * 2 * HIDC + DIMC * QKC + HIDC * DIMC;
    f2b_all<<<(NCV + 255) / 256, 256>>>(Wh, Wqk, Wo, Wc, Wob);
    ln_kernel<<<NTOK, 128>>>((const float4*)x, (const float4*)ln_w,
                             (const float4*)ln_b, (uint2*)normed);

    // 2+3. fused: [h | qk] = silu(normed @ [Wh | Wqk] + [bh | bqk]), epilogues
    {
        EpiParams p{}; p.bias = bh; p.bias2 = bqk; p.gamma = gamma; p.beta = beta;
        p.out_b0 = v; p.out_b1 = gate;
        p.out_b2 = quad_q; p.out_b3 = lin_q; p.out_b4 = quad_k; p.out_b5 = lin_k;
        gemm11<EPI_HQK, 1, 0, 0><<<dim3(NHQ / 128, NTOK / 128, 1), 256, SM1>>>(
            normed, Wc, 0, 0, DIMC, nullptr, nullptr, 0, 0, 0,
            NHQ, DIMC, 0, p);
    }
    // lk^T per group
    transpose_lk<<<dim3(GRP / 32, QKC / 32, NGRP), dim3(32, 8)>>>(lin_k, lkT);

    // 4. S = relu2(QK^T / G), causal (upper block skipped)
    {
        EpiParams p{}; p.out_b0 = S;
        gemm11<EPI_RELU2, 0, 0, 0><<<dim3(2, 2, NGRP), 256, SM0>>>(
            quad_q, quad_k, (long)GRP * QKC, (long)GRP * QKC, QKC,
            nullptr, nullptr, 0, 0, 0, GRP, QKC, 0, p);
    }
    // 6. linkv = lk^T @ V / G
    {
        EpiParams p{}; p.out_f = linkv;
        gemm11<EPI_LINKV, 1, 0, 0><<<dim3(HIDC / 128, 1, NGRP), 256, SM1>>>(
            lkT, v, (long)QKC * GRP, (long)GRP * HIDC, GRP,
            nullptr, nullptr, 0, 0, 0, HIDC, GRP, 0, p);
    }
    // 7. exclusive cumsum over groups
    cumsum_kv<<<(4 * QKC * HIDC / 256), 256>>>(linkv, linkvc);

    // 8. outp = gate * (S@V + lq @ linkvc)    [fused quad + combine]
    {
        EpiParams p{}; p.gate = gate; p.out_b0 = outp;
        gemm11<EPI_COMBINE, 1, 1, 1><<<dim3(HIDC / 128, 2, NGRP), 256, SM1>>>(
            S, v, (long)GRP * GRP, (long)GRP * HIDC, GRP,
            lin_q, linkvc, (long)GRP * QKC, (long)QKC * HIDC, QKC,
            HIDC, GRP, QKC, p);
    }
    // 9. out = outp @ Wo + bo + x
    {
        EpiParams p{}; p.bias = bo; p.bias2 = x; p.out_f = out;
        gemm11<EPI_FINAL, 1, 0, 0><<<dim3(DIMC / 128, NTOK / 128, 1), 256, SM1>>>(
            outp, Wob, 0, 0, HIDC, nullptr, nullptr, 0, 0, 0,
            DIMC, HIDC, 0, p);
    }
}

// round 15
// speedup vs baseline: 1.1602x; 1.0263x over previous
#include <cuda_runtime.h>
#include <cuda_bf16.h>
#include <cstdint>

// ---------------------------------------------------------------------------
// FLASH / GAU block on GB300 — round 14:
//  * R7 base (404.1 us: bf16 HMMA, 3-stage pipeline, packed epilogue stores)
//  * tcgen05 abandoned (ptxas lowers via compute_103 — ISA unreachable)
//  * qk GEMM: M=64 tiles (grid 256 -> fills the chip; was 128 CTAs / 148 SMs)
//  * qk epilogue writes lin_k head directly transposed -> transpose_lk kernel
//    and its 8 MB round trip eliminated
// ---------------------------------------------------------------------------

#define DIMC   512
#define HIDC   1024
#define QKC    128
#define GRP    256
#define NTOK   16384            // 4 * 4096
#define NGRP   64               // 4 * 16
#define GPB    16               // groups per batch

// ------------------------- scratch (device globals) ------------------------
__device__ __nv_bfloat16 g_normed[NTOK * DIMC];
__device__ __nv_bfloat16 g_Whb   [DIMC * 2 * HIDC];
__device__ __nv_bfloat16 g_Wqkb  [DIMC * QKC];
__device__ __nv_bfloat16 g_Wob   [HIDC * DIMC];
__device__ __nv_bfloat16 g_v     [NTOK * HIDC];
__device__ __nv_bfloat16 g_gate  [NTOK * HIDC];
__device__ __nv_bfloat16 g_qh    [3 * NTOK * QKC];      // quad_q, lin_q, quad_k
__device__ __nv_bfloat16 g_lkT   [NGRP * QKC * GRP];    // lin_k, transposed per group
__device__ __nv_bfloat16 g_S     [NGRP * GRP * GRP];
__device__ float         g_linkv [NGRP * QKC * HIDC];
__device__ __nv_bfloat16 g_linkvc[NGRP * QKC * HIDC];
__device__ __nv_bfloat16 g_outp  [NTOK * HIDC];

// ------------------------------ helpers ------------------------------------
__device__ __forceinline__ float silu_f(float v) {
    return v * (1.0f / (1.0f + __expf(-v)));
}

__device__ __forceinline__ uint32_t packbf(float a, float b) {
    __nv_bfloat162 h = __floats2bfloat162_rn(a, b);
    return *(uint32_t*)&h;
}

__device__ __forceinline__ void mma16816(float* c, const uint32_t* a, const uint32_t* b) {
    asm volatile(
        "mma.sync.aligned.m16n8k16.row.col.f32.bf16.bf16.f32 "
        "{%0,%1,%2,%3},{%4,%5,%6,%7},{%8,%9},{%0,%1,%2,%3};\n"
        : "+f"(c[0]), "+f"(c[1]), "+f"(c[2]), "+f"(c[3])
        : "r"(a[0]), "r"(a[1]), "r"(a[2]), "r"(a[3]), "r"(b[0]), "r"(b[1]));
}

__device__ __forceinline__ void cp16(uint32_t dst, const void* src) {
    asm volatile("cp.async.cg.shared.global [%0], [%1], 16;\n" :: "r"(dst), "l"(src));
}
__device__ __forceinline__ void cp_commit() {
    asm volatile("cp.async.commit_group;\n" ::: "memory");
}
__device__ __forceinline__ void cp_wait1() {
    asm volatile("cp.async.wait_group 1;\n" ::: "memory");
}

__device__ __forceinline__ void ldsm4(uint32_t* r, uint32_t a) {
    asm volatile("ldmatrix.sync.aligned.m8n8.x4.shared.b16 {%0,%1,%2,%3},[%4];\n"
        : "=r"(r[0]), "=r"(r[1]), "=r"(r[2]), "=r"(r[3]) : "r"(a));
}
__device__ __forceinline__ void ldsm4t(uint32_t* r, uint32_t a) {
    asm volatile("ldmatrix.sync.aligned.m8n8.x4.trans.shared.b16 {%0,%1,%2,%3},[%4];\n"
        : "=r"(r[0]), "=r"(r[1]), "=r"(r[2]), "=r"(r[3]) : "r"(a));
}

struct EpiParams {
    const float* bias;
    const float* x;                 // final residual
    const __nv_bfloat16* gate;
    const float* gamma;
    const float* beta;
    float* out_f;
    __nv_bfloat16* out_b0;
    __nv_bfloat16* out_b1;
    __nv_bfloat16* out_b2;
    __nv_bfloat16* out_b3;          // lkT for EPI_QK
};

#define EPI_H       0
#define EPI_QK      1
#define EPI_RELU2   2
#define EPI_LINKV   4
#define EPI_COMBINE 5
#define EPI_FINAL   6

// packed epilogue: handles the (n, n+1) accumulator pair with wide stores
template<int EPI>
__device__ __forceinline__ void epi_store2(const EpiParams& p, int z, int m, int n,
                                           float a0, float a1) {
    if constexpr (EPI == EPI_H) {
        float v0 = silu_f(a0 + p.bias[n]);
        float v1 = silu_f(a1 + p.bias[n + 1]);
        uint32_t u = packbf(v0, v1);
        if (n < HIDC) *(uint32_t*)(p.out_b0 + (long)m * HIDC + n)        = u;
        else          *(uint32_t*)(p.out_b1 + (long)m * HIDC + n - HIDC) = u;
    } else if constexpr (EPI == EPI_QK) {
        float v0 = silu_f(a0 + p.bias[n]);
        float v1 = silu_f(a1 + p.bias[n + 1]);
        long o = (long)m * QKC + n;
        *(uint32_t*)(p.out_b0 + o) = packbf(v0 * p.gamma[n]           + p.beta[n],
                                            v1 * p.gamma[n + 1]       + p.beta[n + 1]);
        *(uint32_t*)(p.out_b1 + o) = packbf(v0 * p.gamma[QKC + n]     + p.beta[QKC + n],
                                            v1 * p.gamma[QKC + n + 1] + p.beta[QKC + n + 1]);
        *(uint32_t*)(p.out_b2 + o) = packbf(v0 * p.gamma[2 * QKC + n]     + p.beta[2 * QKC + n],
                                            v1 * p.gamma[2 * QKC + n + 1] + p.beta[2 * QKC + n + 1]);
        // lin_k head: store TRANSPOSED into lkT[z][d][t]  (z = m>>8, t = m&255)
        float h3a = v0 * p.gamma[3 * QKC + n]     + p.beta[3 * QKC + n];
        float h3b = v1 * p.gamma[3 * QKC + n + 1] + p.beta[3 * QKC + n + 1];
        __nv_bfloat16* lb = p.out_b3 + (long)(m >> 8) * QKC * GRP + (m & 255);
        lb[(long)n * GRP]       = __float2bfloat16(h3a);
        lb[(long)(n + 1) * GRP] = __float2bfloat16(h3b);
    } else if constexpr (EPI == EPI_RELU2) {
        float s0 = fmaxf(a0 * (1.0f / GRP), 0.0f); s0 *= s0;
        float s1 = fmaxf(a1 * (1.0f / GRP), 0.0f); s1 *= s1;
        if (n > m)     s0 = 0.0f;    // causal within group
        if (n + 1 > m) s1 = 0.0f;
        *(uint32_t*)(p.out_b0 + (long)z * GRP * GRP + m * GRP + n) = packbf(s0, s1);
    } else if constexpr (EPI == EPI_LINKV) {
        float2 r = make_float2(a0 * (1.0f / GRP), a1 * (1.0f / GRP));
        *(float2*)(p.out_f + (long)z * QKC * HIDC + (long)m * HIDC + n) = r;
    } else if constexpr (EPI == EPI_COMBINE) {
        long o = (long)z * GRP * HIDC + (long)m * HIDC + n;
        uint32_t gu = *(const uint32_t*)(p.gate + o);
        __nv_bfloat162 gh = *(__nv_bfloat162*)&gu;
        *(uint32_t*)(p.out_b0 + o) = packbf(__bfloat162float(gh.x) * a0,
                                            __bfloat162float(gh.y) * a1);
    } else { // EPI_FINAL
        long o = (long)m * DIMC + n;
        float2 xr = *(const float2*)(p.x + o);
        float2 r = make_float2(a0 + p.bias[n] + xr.x, a1 + p.bias[n + 1] + xr.y);
        *(float2*)(p.out_f + o) = r;
    }
}

// ---------------------------------------------------------------------------
// 3-stage pipelined bf16 GEMM with optional dual-source accumulation.
//   C[M,N] = A[M,K1] @ B  (+ A2[M,K2] @ B2 if DUAL)
//   BLAY == 0: B is [N,K] row-major (K-contiguous)   (ldb == K1)
//   BLAY == 1: B is [K,N] row-major (N-contiguous)   (ldb == N)
//   CAUSALA:   trim K1 to (bm+1)*BM (S@V pair: S lower-triangular)
//   MT: m-tiles per warp (4 -> BM=128, 2 -> BM=64)
// Block tile BMx128, k-tile 32, 256 threads, 8 warps 2(M)x4(N).
// ---------------------------------------------------------------------------
template<int EPI, int BLAY, int CAUSALA, int DUAL, int MT>
__global__ __launch_bounds__(256) void gemm14(
    const __nv_bfloat16* __restrict__ A,  const __nv_bfloat16* __restrict__ B,
    long sAz, long sBz, int lda1,
    const __nv_bfloat16* __restrict__ A2, const __nv_bfloat16* __restrict__ B2,
    long sA2z, long sB2z, int lda2,
    int N, int K1, int K2, EpiParams p)
{
    constexpr int BM  = 32 * MT;                            // 128 or 64
    constexpr int SAE = BM * 40;                            // A stage elems
    constexpr int SBE = (BLAY == 1) ? 32 * 136 : 128 * 40;  // B stage elems
    extern __shared__ __nv_bfloat16 dsm[];

    const int z  = blockIdx.z;
    const int bm = blockIdx.y;
    const int bn = blockIdx.x;
    if constexpr (EPI == EPI_RELU2) { if (bn > bm) return; }   // fully masked tile

    const __nv_bfloat16* A1b = A  + (long)z * sAz;
    const __nv_bfloat16* B1b = B  + (long)z * sBz;
    const __nv_bfloat16* A2b = DUAL ? (A2 + (long)z * sA2z) : nullptr;
    const __nv_bfloat16* B2b = DUAL ? (B2 + (long)z * sB2z) : nullptr;

    const int t    = threadIdx.x;
    const int wid  = t >> 5;
    const int lane = t & 31;
    const int wm   = wid & 1;        // 0..1  (BM/2 rows each)
    const int wn   = wid >> 1;       // 0..3  (32 cols each)
    const int gID  = lane >> 2;      // 0..7
    const int tg   = lane & 3;       // 0..3

    const int Keff1 = CAUSALA ? ((bm + 1) * BM < K1 ? (bm + 1) * BM : K1) : K1;
    const int nk1 = Keff1 >> 5;
    const int nk2 = DUAL ? (K2 >> 5) : 0;
    const int nt  = nk1 + nk2;

    const uint32_t sAu = (uint32_t)__cvta_generic_to_shared(dsm);
    const uint32_t sBu = sAu + 3 * SAE * 2;

    float acc[MT][4][4];
    #pragma unroll
    for (int i = 0; i < MT; i++)
        #pragma unroll
        for (int j = 0; j < 4; j++)
            #pragma unroll
            for (int r = 0; r < 4; r++) acc[i][j][r] = 0.0f;

    // ---- stage loader (all cp.async) ----
    auto load_stage = [&](int st, int gt) {
        const __nv_bfloat16* Ab;
        const __nv_bfloat16* Bb;
        int lda, k0;
        if (!DUAL || gt < nk1) { Ab = A1b; Bb = B1b; lda = lda1; k0 = gt * 32; }
        else                   { Ab = A2b; Bb = B2b; lda = lda2; k0 = (gt - nk1) * 32; }
        {   // A tile: [BM rows, 32 k] -> sA[st][row*40 + k]
            int r = t >> 2, c = (t & 3) * 8;
            uint32_t d = sAu + (uint32_t)(st * SAE + r * 40 + c) * 2;
            cp16(d, Ab + (long)(bm * BM + r) * lda + k0 + c);
            if constexpr (MT == 4)
                cp16(d + 64 * 40 * 2, Ab + (long)(bm * BM + r + 64) * lda + k0 + c);
        }
        if (BLAY == 0) {   // B [N,K]: sB[st][n*40 + k]  (ldb == K1)
            int r = t >> 2, c = (t & 3) * 8;
            uint32_t d = sBu + (uint32_t)(st * SBE + r * 40 + c) * 2;
            cp16(d,                Bb + (long)(bn * 128 + r)      * K1 + k0 + c);
            cp16(d + 64 * 40 * 2,  Bb + (long)(bn * 128 + r + 64) * K1 + k0 + c);
        } else {           // B [K,N]: sB[st][k*136 + n]  (ldb == N)
            int r = t >> 4, c = (t & 15) * 8;
            uint32_t d = sBu + (uint32_t)(st * SBE + r * 136 + c) * 2;
            cp16(d,                 Bb + (long)(k0 + r)      * N + bn * 128 + c);
            cp16(d + 16 * 136 * 2,  Bb + (long)(k0 + r + 16) * N + bn * 128 + c);
        }
    };

    // prologue: stages 0 and 1 (all call sites have nt >= 2)
    load_stage(0, 0); cp_commit();
    load_stage(1, 1); cp_commit();

    for (int gt = 0; gt < nt; gt++) {
        if (gt + 2 < nt) load_stage((gt + 2) % 3, gt + 2);
        cp_commit();
        cp_wait1();
        __syncthreads();

        const int st = gt % 3;
        const uint32_t aB = sAu + (uint32_t)(st * SAE) * 2;
        const uint32_t bB = sBu + (uint32_t)(st * SBE) * 2;

        #pragma unroll
        for (int kk = 0; kk < 32; kk += 16) {
            uint32_t af[MT][4];
            #pragma unroll
            for (int mt = 0; mt < MT; mt++) {
                uint32_t a = aB + (uint32_t)((wm * (BM / 2) + mt * 16 + (lane & 15)) * 40
                                             + kk + ((lane >> 4) * 8)) * 2;
                ldsm4(af[mt], a);
            }
            uint32_t bfr[2][4];
            #pragma unroll
            for (int h = 0; h < 2; h++) {
                int n0 = wn * 32 + h * 16;
                if (BLAY == 0) {
                    uint32_t a = bB + (uint32_t)((n0 + (lane & 7) + ((lane >> 4) << 3)) * 40
                                                 + kk + (((lane >> 3) & 1) * 8)) * 2;
                    ldsm4(bfr[h], a);
                } else {
                    uint32_t a = bB + (uint32_t)((kk + (lane & 15)) * 136
                                                 + n0 + ((lane >> 4) * 8)) * 2;
                    ldsm4t(bfr[h], a);
                }
            }
            #pragma unroll
            for (int mt = 0; mt < MT; mt++)
                #pragma unroll
                for (int j = 0; j < 4; j++) {
                    uint32_t bb[2] = { bfr[j >> 1][(j & 1) * 2],
                                       bfr[j >> 1][(j & 1) * 2 + 1] };
                    mma16816(acc[mt][j], af[mt], bb);
                }
        }
        __syncthreads();
    }

    #pragma unroll
    for (int mt = 0; mt < MT; mt++)
        #pragma unroll
        for (int j = 0; j < 4; j++) {
            int m0 = bm * BM + wm * (BM / 2) + mt * 16 + gID;
            int n0 = bn * 128 + wn * 32 + j * 8 + tg * 2;
            epi_store2<EPI>(p, z, m0,     n0, acc[mt][j][0], acc[mt][j][1]);
            epi_store2<EPI>(p, z, m0 + 8, n0, acc[mt][j][2], acc[mt][j][3]);
        }
}

// ----------------------------- small kernels --------------------------------
// single kernel converting all three weight matrices fp32 -> bf16
__global__ void f2b_all(const float* __restrict__ Wh, const float* __restrict__ Wqk,
                        const float* __restrict__ Wo,
                        __nv_bfloat16* __restrict__ Whb, __nv_bfloat16* __restrict__ Wqkb,
                        __nv_bfloat16* __restrict__ Wob) {
    const int N1 = DIMC * 2 * HIDC;          // 1048576
    const int N2 = DIMC * QKC;               // 65536
    const int N3 = HIDC * DIMC;              // 524288
    int i = blockIdx.x * 256 + threadIdx.x;
    if (i < N1) Whb[i] = __float2bfloat16(Wh[i]);
    else if (i < N1 + N2) Wqkb[i - N1] = __float2bfloat16(Wqk[i - N1]);
    else if (i < N1 + N2 + N3) Wob[i - N1 - N2] = __float2bfloat16(Wo[i - N1 - N2]);
}

// 128 threads, float4 loads, bf16x2 packed stores
__global__ void ln_kernel(const float4* __restrict__ x4, const float4* __restrict__ w4,
                          const float4* __restrict__ b4, uint2* __restrict__ out) {
    int tok = blockIdx.x;
    int t = threadIdx.x;
    float4 v = x4[(long)tok * 128 + t];
    float s  = v.x + v.y + v.z + v.w;
    float sq = v.x * v.x + v.y * v.y + v.z * v.z + v.w * v.w;
    #pragma unroll
    for (int o = 16; o; o >>= 1) {
        s  += __shfl_xor_sync(0xffffffffu, s,  o);
        sq += __shfl_xor_sync(0xffffffffu, sq, o);
    }
    __shared__ float ss[4], sv[4];
    if ((t & 31) == 0) { ss[t >> 5] = s; sv[t >> 5] = sq; }
    __syncthreads();
    float S = ss[0] + ss[1] + ss[2] + ss[3];
    float Q = sv[0] + sv[1] + sv[2] + sv[3];
    float mu  = S * (1.0f / DIMC);
    float var = Q * (1.0f / DIMC) - mu * mu;
    float rs  = rsqrtf(var + 1e-5f);
    float4 w = w4[t], b = b4[t];
    float r0 = (v.x - mu) * rs * w.x + b.x;
    float r1 = (v.y - mu) * rs * w.y + b.y;
    float r2 = (v.z - mu) * rs * w.z + b.z;
    float r3 = (v.w - mu) * rs * w.w + b.w;
    uint2 u;
    u.x = packbf(r0, r1);
    u.y = packbf(r2, r3);
    out[(long)tok * 128 + t] = u;
}

// exclusive cumsum over groups (g dim), fp32 in -> bf16 out
__global__ void cumsum_kv(const float* __restrict__ kv, __nv_bfloat16* __restrict__ out) {
    long i = (long)blockIdx.x * 256 + threadIdx.x;
    const long GE = (long)QKC * HIDC;                 // 131072
    if (i >= 4 * GE) return;
    int  bb = (int)(i / GE);
    long e  = i % GE;
    float s = 0.0f;
    #pragma unroll
    for (int g = 0; g < GPB; g++) {
        long o = ((long)(bb * GPB + g)) * GE + e;
        out[o] = __float2bfloat16(s);
        s += kv[o];
    }
}

// ------------------------------- launcher -----------------------------------
extern "C" void kernel_launch(void* const* d_in, const int* in_sizes, int n_in,
                              void* d_out, int out_size) {
    const float* x     = (const float*)d_in[0];
    const float* ln_w  = (const float*)d_in[1];
    const float* ln_b  = (const float*)d_in[2];
    const float* Wh    = (const float*)d_in[3];
    const float* bh    = (const float*)d_in[4];
    const float* Wqk   = (const float*)d_in[5];
    const float* bqk   = (const float*)d_in[6];
    const float* gamma = (const float*)d_in[7];
    const float* beta  = (const float*)d_in[8];
    const float* Wo    = (const float*)d_in[9];
    const float* bo    = (const float*)d_in[10];
    float* out = (float*)d_out;

    __nv_bfloat16 *normed, *Whb, *Wqkb, *Wob, *v, *gate, *qh, *lkT, *S, *linkvc, *outp;
    float *linkv;
    cudaGetSymbolAddress((void**)&normed, g_normed);
    cudaGetSymbolAddress((void**)&Whb,    g_Whb);
    cudaGetSymbolAddress((void**)&Wqkb,   g_Wqkb);
    cudaGetSymbolAddress((void**)&Wob,    g_Wob);
    cudaGetSymbolAddress((void**)&v,      g_v);
    cudaGetSymbolAddress((void**)&gate,   g_gate);
    cudaGetSymbolAddress((void**)&qh,     g_qh);
    cudaGetSymbolAddress((void**)&lkT,    g_lkT);
    cudaGetSymbolAddress((void**)&S,      g_S);
    cudaGetSymbolAddress((void**)&linkv,  g_linkv);
    cudaGetSymbolAddress((void**)&linkvc, g_linkvc);
    cudaGetSymbolAddress((void**)&outp,   g_outp);

    const long HSZ = (long)NTOK * QKC;   // per-head size
    __nv_bfloat16* quad_q = qh;
    __nv_bfloat16* lin_q  = qh + HSZ;
    __nv_bfloat16* quad_k = qh + 2 * HSZ;

    // dynamic smem sizes (3 stages)
    const int SM1   = 3 * (128 * 40 + 32 * 136) * 2;   // 56832
    const int SM1_64= 3 * (64 * 40 + 32 * 136) * 2;    // 41472
    const int SM0   = 3 * (128 * 40 + 128 * 40) * 2;   // 61440
    cudaFuncSetAttribute((const void*)gemm14<EPI_H,       1, 0, 0, 4>, cudaFuncAttributeMaxDynamicSharedMemorySize, SM1);
    cudaFuncSetAttribute((const void*)gemm14<EPI_QK,      1, 0, 0, 2>, cudaFuncAttributeMaxDynamicSharedMemorySize, SM1_64);
    cudaFuncSetAttribute((const void*)gemm14<EPI_RELU2,   0, 0, 0, 4>, cudaFuncAttributeMaxDynamicSharedMemorySize, SM0);
    cudaFuncSetAttribute((const void*)gemm14<EPI_LINKV,   1, 0, 0, 4>, cudaFuncAttributeMaxDynamicSharedMemorySize, SM1);
    cudaFuncSetAttribute((const void*)gemm14<EPI_COMBINE, 1, 1, 1, 4>, cudaFuncAttributeMaxDynamicSharedMemorySize, SM1);
    cudaFuncSetAttribute((const void*)gemm14<EPI_FINAL,   1, 0, 0, 4>, cudaFuncAttributeMaxDynamicSharedMemorySize, SM1);

    // 1. weight converts + layernorm
    const int NCV = DIMC * 2 * HIDC + DIMC * QKC + HIDC * DIMC;
    f2b_all<<<(NCV + 255) / 256, 256>>>(Wh, Wqk, Wo, Whb, Wqkb, Wob);
    ln_kernel<<<NTOK, 128>>>((const float4*)x, (const float4*)ln_w,
                             (const float4*)ln_b, (uint2*)normed);

    // 2. h = silu(normed @ Wh + bh) -> v, gate
    {
        EpiParams p{}; p.bias = bh; p.out_b0 = v; p.out_b1 = gate;
        gemm14<EPI_H, 1, 0, 0, 4><<<dim3(2 * HIDC / 128, NTOK / 128, 1), 256, SM1>>>(
            normed, Whb, 0, 0, DIMC, nullptr, nullptr, 0, 0, 0,
            2 * HIDC, DIMC, 0, p);
    }
    // 3. qk heads (M=64 tiles -> 256 CTAs; lin_k written transposed into lkT)
    {
        EpiParams p{}; p.bias = bqk; p.gamma = gamma; p.beta = beta;
        p.out_b0 = quad_q; p.out_b1 = lin_q; p.out_b2 = quad_k; p.out_b3 = lkT;
        gemm14<EPI_QK, 1, 0, 0, 2><<<dim3(1, NTOK / 64, 1), 256, SM1_64>>>(
            normed, Wqkb, 0, 0, DIMC, nullptr, nullptr, 0, 0, 0,
            QKC, DIMC, 0, p);
    }
    // 4. S = relu2(QK^T / G), causal (upper block skipped)
    {
        EpiParams p{}; p.out_b0 = S;
        gemm14<EPI_RELU2, 0, 0, 0, 4><<<dim3(2, 2, NGRP), 256, SM0>>>(
            quad_q, quad_k, (long)GRP * QKC, (long)GRP * QKC, QKC,
            nullptr, nullptr, 0, 0, 0, GRP, QKC, 0, p);
    }
    // 6. linkv = lk^T @ V / G
    {
        EpiParams p{}; p.out_f = linkv;
        gemm14<EPI_LINKV, 1, 0, 0, 4><<<dim3(HIDC / 128, 1, NGRP), 256, SM1>>>(
            lkT, v, (long)QKC * GRP, (long)GRP * HIDC, GRP,
            nullptr, nullptr, 0, 0, 0, HIDC, GRP, 0, p);
    }
    // 7. exclusive cumsum over groups
    cumsum_kv<<<(4 * QKC * HIDC / 256), 256>>>(linkv, linkvc);

    // 8. outp = gate * (S@V + lq @ linkvc)    [fused quad + combine]
    {
        EpiParams p{}; p.gate = gate; p.out_b0 = outp;
        gemm14<EPI_COMBINE, 1, 1, 1, 4><<<dim3(HIDC / 128, 2, NGRP), 256, SM1>>>(
            S, v, (long)GRP * GRP, (long)GRP * HIDC, GRP,
            lin_q, linkvc, (long)GRP * QKC, (long)QKC * HIDC, QKC,
            HIDC, GRP, QKC, p);
    }
    // 9. out = outp @ Wo + bo + x
    {
        EpiParams p{}; p.bias = bo; p.x = x; p.out_f = out;
        gemm14<EPI_FINAL, 1, 0, 0, 4><<<dim3(DIMC / 128, NTOK / 128, 1), 256, SM1>>>(
            outp, Wob, 0, 0, HIDC, nullptr, nullptr, 0, 0, 0,
            DIMC, HIDC, 0, p);
    }
}

// round 16
// speedup vs baseline: 1.2084x; 1.0416x over previous
#include <cuda_runtime.h>
#include <cuda_bf16.h>
#include <cstdint>

// ---------------------------------------------------------------------------
// FLASH / GAU block on GB300 — round 15:
//  * R14 base (397.8 us) + K-tile 64 for all KN GEMMs (template KT):
//    half the barriers per FLOP, 2x prefetch lookahead, 2 CTAs/SM preserved
//  * relu2 (NK layout) stays KT=32
// ---------------------------------------------------------------------------

#define DIMC   512
#define HIDC   1024
#define QKC    128
#define GRP    256
#define NTOK   16384            // 4 * 4096
#define NGRP   64               // 4 * 16
#define GPB    16               // groups per batch

// ------------------------- scratch (device globals) ------------------------
__device__ __nv_bfloat16 g_normed[NTOK * DIMC];
__device__ __nv_bfloat16 g_Whb   [DIMC * 2 * HIDC];
__device__ __nv_bfloat16 g_Wqkb  [DIMC * QKC];
__device__ __nv_bfloat16 g_Wob   [HIDC * DIMC];
__device__ __nv_bfloat16 g_v     [NTOK * HIDC];
__device__ __nv_bfloat16 g_gate  [NTOK * HIDC];
__device__ __nv_bfloat16 g_qh    [3 * NTOK * QKC];      // quad_q, lin_q, quad_k
__device__ __nv_bfloat16 g_lkT   [NGRP * QKC * GRP];    // lin_k, transposed per group
__device__ __nv_bfloat16 g_S     [NGRP * GRP * GRP];
__device__ float         g_linkv [NGRP * QKC * HIDC];
__device__ __nv_bfloat16 g_linkvc[NGRP * QKC * HIDC];
__device__ __nv_bfloat16 g_outp  [NTOK * HIDC];

// ------------------------------ helpers ------------------------------------
__device__ __forceinline__ float silu_f(float v) {
    return v * (1.0f / (1.0f + __expf(-v)));
}

__device__ __forceinline__ uint32_t packbf(float a, float b) {
    __nv_bfloat162 h = __floats2bfloat162_rn(a, b);
    return *(uint32_t*)&h;
}

__device__ __forceinline__ void mma16816(float* c, const uint32_t* a, const uint32_t* b) {
    asm volatile(
        "mma.sync.aligned.m16n8k16.row.col.f32.bf16.bf16.f32 "
        "{%0,%1,%2,%3},{%4,%5,%6,%7},{%8,%9},{%0,%1,%2,%3};\n"
        : "+f"(c[0]), "+f"(c[1]), "+f"(c[2]), "+f"(c[3])
        : "r"(a[0]), "r"(a[1]), "r"(a[2]), "r"(a[3]), "r"(b[0]), "r"(b[1]));
}

__device__ __forceinline__ void cp16(uint32_t dst, const void* src) {
    asm volatile("cp.async.cg.shared.global [%0], [%1], 16;\n" :: "r"(dst), "l"(src));
}
__device__ __forceinline__ void cp_commit() {
    asm volatile("cp.async.commit_group;\n" ::: "memory");
}
__device__ __forceinline__ void cp_wait1() {
    asm volatile("cp.async.wait_group 1;\n" ::: "memory");
}

__device__ __forceinline__ void ldsm4(uint32_t* r, uint32_t a) {
    asm volatile("ldmatrix.sync.aligned.m8n8.x4.shared.b16 {%0,%1,%2,%3},[%4];\n"
        : "=r"(r[0]), "=r"(r[1]), "=r"(r[2]), "=r"(r[3]) : "r"(a));
}
__device__ __forceinline__ void ldsm4t(uint32_t* r, uint32_t a) {
    asm volatile("ldmatrix.sync.aligned.m8n8.x4.trans.shared.b16 {%0,%1,%2,%3},[%4];\n"
        : "=r"(r[0]), "=r"(r[1]), "=r"(r[2]), "=r"(r[3]) : "r"(a));
}

struct EpiParams {
    const float* bias;
    const float* x;                 // final residual
    const __nv_bfloat16* gate;
    const float* gamma;
    const float* beta;
    float* out_f;
    __nv_bfloat16* out_b0;
    __nv_bfloat16* out_b1;
    __nv_bfloat16* out_b2;
    __nv_bfloat16* out_b3;          // lkT for EPI_QK
};

#define EPI_H       0
#define EPI_QK      1
#define EPI_RELU2   2
#define EPI_LINKV   4
#define EPI_COMBINE 5
#define EPI_FINAL   6

// packed epilogue: handles the (n, n+1) accumulator pair with wide stores
template<int EPI>
__device__ __forceinline__ void epi_store2(const EpiParams& p, int z, int m, int n,
                                           float a0, float a1) {
    if constexpr (EPI == EPI_H) {
        float v0 = silu_f(a0 + p.bias[n]);
        float v1 = silu_f(a1 + p.bias[n + 1]);
        uint32_t u = packbf(v0, v1);
        if (n < HIDC) *(uint32_t*)(p.out_b0 + (long)m * HIDC + n)        = u;
        else          *(uint32_t*)(p.out_b1 + (long)m * HIDC + n - HIDC) = u;
    } else if constexpr (EPI == EPI_QK) {
        float v0 = silu_f(a0 + p.bias[n]);
        float v1 = silu_f(a1 + p.bias[n + 1]);
        long o = (long)m * QKC + n;
        *(uint32_t*)(p.out_b0 + o) = packbf(v0 * p.gamma[n]           + p.beta[n],
                                            v1 * p.gamma[n + 1]       + p.beta[n + 1]);
        *(uint32_t*)(p.out_b1 + o) = packbf(v0 * p.gamma[QKC + n]     + p.beta[QKC + n],
                                            v1 * p.gamma[QKC + n + 1] + p.beta[QKC + n + 1]);
        *(uint32_t*)(p.out_b2 + o) = packbf(v0 * p.gamma[2 * QKC + n]     + p.beta[2 * QKC + n],
                                            v1 * p.gamma[2 * QKC + n + 1] + p.beta[2 * QKC + n + 1]);
        // lin_k head: store TRANSPOSED into lkT[z][d][t]  (z = m>>8, t = m&255)
        float h3a = v0 * p.gamma[3 * QKC + n]     + p.beta[3 * QKC + n];
        float h3b = v1 * p.gamma[3 * QKC + n + 1] + p.beta[3 * QKC + n + 1];
        __nv_bfloat16* lb = p.out_b3 + (long)(m >> 8) * QKC * GRP + (m & 255);
        lb[(long)n * GRP]       = __float2bfloat16(h3a);
        lb[(long)(n + 1) * GRP] = __float2bfloat16(h3b);
    } else if constexpr (EPI == EPI_RELU2) {
        float s0 = fmaxf(a0 * (1.0f / GRP), 0.0f); s0 *= s0;
        float s1 = fmaxf(a1 * (1.0f / GRP), 0.0f); s1 *= s1;
        if (n > m)     s0 = 0.0f;    // causal within group
        if (n + 1 > m) s1 = 0.0f;
        *(uint32_t*)(p.out_b0 + (long)z * GRP * GRP + m * GRP + n) = packbf(s0, s1);
    } else if constexpr (EPI == EPI_LINKV) {
        float2 r = make_float2(a0 * (1.0f / GRP), a1 * (1.0f / GRP));
        *(float2*)(p.out_f + (long)z * QKC * HIDC + (long)m * HIDC + n) = r;
    } else if constexpr (EPI == EPI_COMBINE) {
        long o = (long)z * GRP * HIDC + (long)m * HIDC + n;
        uint32_t gu = *(const uint32_t*)(p.gate + o);
        __nv_bfloat162 gh = *(__nv_bfloat162*)&gu;
        *(uint32_t*)(p.out_b0 + o) = packbf(__bfloat162float(gh.x) * a0,
                                            __bfloat162float(gh.y) * a1);
    } else { // EPI_FINAL
        long o = (long)m * DIMC + n;
        float2 xr = *(const float2*)(p.x + o);
        float2 r = make_float2(a0 + p.bias[n] + xr.x, a1 + p.bias[n + 1] + xr.y);
        *(float2*)(p.out_f + o) = r;
    }
}

// ---------------------------------------------------------------------------
// 3-stage pipelined bf16 GEMM with optional dual-source accumulation.
//   C[M,N] = A[M,K1] @ B  (+ A2[M,K2] @ B2 if DUAL)
//   BLAY == 0: B is [N,K] row-major (K-contiguous)   (ldb == K1), KT must be 32
//   BLAY == 1: B is [K,N] row-major (N-contiguous)   (ldb == N)
//   CAUSALA:   trim K1 to (bm+1)*BM (S@V pair: S lower-triangular)
//   MT: m-tiles per warp (4 -> BM=128, 2 -> BM=64)
//   KT: k-tile depth in elements (32 or 64); A row stride = KT+8
// Block tile BMx128, 256 threads, 8 warps 2(M)x4(N).
// ---------------------------------------------------------------------------
template<int EPI, int BLAY, int CAUSALA, int DUAL, int MT, int KT>
__global__ __launch_bounds__(256) void gemm15(
    const __nv_bfloat16* __restrict__ A,  const __nv_bfloat16* __restrict__ B,
    long sAz, long sBz, int lda1,
    const __nv_bfloat16* __restrict__ A2, const __nv_bfloat16* __restrict__ B2,
    long sA2z, long sB2z, int lda2,
    int N, int K1, int K2, EpiParams p)
{
    constexpr int BM  = 32 * MT;                            // 128 or 64
    constexpr int AST = KT + 8;                             // A smem row stride
    constexpr int SAE = BM * AST;                           // A stage elems
    constexpr int SBE = (BLAY == 1) ? KT * 136 : 128 * 40;  // B stage elems
    extern __shared__ __nv_bfloat16 dsm[];

    const int z  = blockIdx.z;
    const int bm = blockIdx.y;
    const int bn = blockIdx.x;
    if constexpr (EPI == EPI_RELU2) { if (bn > bm) return; }   // fully masked tile

    const __nv_bfloat16* A1b = A  + (long)z * sAz;
    const __nv_bfloat16* B1b = B  + (long)z * sBz;
    const __nv_bfloat16* A2b = DUAL ? (A2 + (long)z * sA2z) : nullptr;
    const __nv_bfloat16* B2b = DUAL ? (B2 + (long)z * sB2z) : nullptr;

    const int t    = threadIdx.x;
    const int wid  = t >> 5;
    const int lane = t & 31;
    const int wm   = wid & 1;        // 0..1  (BM/2 rows each)
    const int wn   = wid >> 1;       // 0..3  (32 cols each)
    const int gID  = lane >> 2;      // 0..7
    const int tg   = lane & 3;       // 0..3

    const int Keff1 = CAUSALA ? ((bm + 1) * BM < K1 ? (bm + 1) * BM : K1) : K1;
    const int nk1 = Keff1 / KT;
    const int nk2 = DUAL ? (K2 / KT) : 0;
    const int nt  = nk1 + nk2;

    const uint32_t sAu = (uint32_t)__cvta_generic_to_shared(dsm);
    const uint32_t sBu = sAu + 3 * SAE * 2;

    float acc[MT][4][4];
    #pragma unroll
    for (int i = 0; i < MT; i++)
        #pragma unroll
        for (int j = 0; j < 4; j++)
            #pragma unroll
            for (int r = 0; r < 4; r++) acc[i][j][r] = 0.0f;

    // ---- stage loader (all cp.async) ----
    auto load_stage = [&](int st, int gt) {
        const __nv_bfloat16* Ab;
        const __nv_bfloat16* Bb;
        int lda, k0;
        if (!DUAL || gt < nk1) { Ab = A1b; Bb = B1b; lda = lda1; k0 = gt * KT; }
        else                   { Ab = A2b; Bb = B2b; lda = lda2; k0 = (gt - nk1) * KT; }
        {   // A tile: [BM rows, KT k] -> sA[st][row*AST + k]
            constexpr int TPR = KT / 8;          // threads per A row
            constexpr int RPP = 256 / TPR;       // rows per pass
            int r = t / TPR, c = (t % TPR) * 8;
            #pragma unroll
            for (int rr = 0; rr < BM; rr += RPP) {
                uint32_t d = sAu + (uint32_t)(st * SAE + (r + rr) * AST + c) * 2;
                cp16(d, Ab + (long)(bm * BM + r + rr) * lda + k0 + c);
            }
        }
        if (BLAY == 0) {   // B [N,K]: sB[st][n*40 + k]  (ldb == K1), KT == 32
            int r = t >> 2, c = (t & 3) * 8;
            uint32_t d = sBu + (uint32_t)(st * SBE + r * 40 + c) * 2;
            cp16(d,                Bb + (long)(bn * 128 + r)      * K1 + k0 + c);
            cp16(d + 64 * 40 * 2,  Bb + (long)(bn * 128 + r + 64) * K1 + k0 + c);
        } else {           // B [K,N]: sB[st][k*136 + n]  (ldb == N)
            int r = t >> 4, c = (t & 15) * 8;
            #pragma unroll
            for (int rr = 0; rr < KT; rr += 16) {
                uint32_t d = sBu + (uint32_t)(st * SBE + (r + rr) * 136 + c) * 2;
                cp16(d, Bb + (long)(k0 + r + rr) * N + bn * 128 + c);
            }
        }
    };

    // prologue: stages 0 and 1 (all call sites have nt >= 2)
    load_stage(0, 0); cp_commit();
    load_stage(1, 1); cp_commit();

    for (int gt = 0; gt < nt; gt++) {
        if (gt + 2 < nt) load_stage((gt + 2) % 3, gt + 2);
        cp_commit();
        cp_wait1();
        __syncthreads();

        const int st = gt % 3;
        const uint32_t aB = sAu + (uint32_t)(st * SAE) * 2;
        const uint32_t bB = sBu + (uint32_t)(st * SBE) * 2;

        #pragma unroll
        for (int kk = 0; kk < KT; kk += 16) {
            uint32_t af[MT][4];
            #pragma unroll
            for (int mt = 0; mt < MT; mt++) {
                uint32_t a = aB + (uint32_t)((wm * (BM / 2) + mt * 16 + (lane & 15)) * AST
                                             + kk + ((lane >> 4) * 8)) * 2;
                ldsm4(af[mt], a);
            }
            uint32_t bfr[2][4];
            #pragma unroll
            for (int h = 0; h < 2; h++) {
                int n0 = wn * 32 + h * 16;
                if (BLAY == 0) {
                    uint32_t a = bB + (uint32_t)((n0 + (lane & 7) + ((lane >> 4) << 3)) * 40
                                                 + kk + (((lane >> 3) & 1) * 8)) * 2;
                    ldsm4(bfr[h], a);
                } else {
                    uint32_t a = bB + (uint32_t)((kk + (lane & 15)) * 136
                                                 + n0 + ((lane >> 4) * 8)) * 2;
                    ldsm4t(bfr[h], a);
                }
            }
            #pragma unroll
            for (int mt = 0; mt < MT; mt++)
                #pragma unroll
                for (int j = 0; j < 4; j++) {
                    uint32_t bb[2] = { bfr[j >> 1][(j & 1) * 2],
                                       bfr[j >> 1][(j & 1) * 2 + 1] };
                    mma16816(acc[mt][j], af[mt], bb);
                }
        }
        __syncthreads();
    }

    #pragma unroll
    for (int mt = 0; mt < MT; mt++)
        #pragma unroll
        for (int j = 0; j < 4; j++) {
            int m0 = bm * BM + wm * (BM / 2) + mt * 16 + gID;
            int n0 = bn * 128 + wn * 32 + j * 8 + tg * 2;
            epi_store2<EPI>(p, z, m0,     n0, acc[mt][j][0], acc[mt][j][1]);
            epi_store2<EPI>(p, z, m0 + 8, n0, acc[mt][j][2], acc[mt][j][3]);
        }
}

// ----------------------------- small kernels --------------------------------
// single kernel converting all three weight matrices fp32 -> bf16
__global__ void f2b_all(const float* __restrict__ Wh, const float* __restrict__ Wqk,
                        const float* __restrict__ Wo,
                        __nv_bfloat16* __restrict__ Whb, __nv_bfloat16* __restrict__ Wqkb,
                        __nv_bfloat16* __restrict__ Wob) {
    const int N1 = DIMC * 2 * HIDC;          // 1048576
    const int N2 = DIMC * QKC;               // 65536
    const int N3 = HIDC * DIMC;              // 524288
    int i = blockIdx.x * 256 + threadIdx.x;
    if (i < N1) Whb[i] = __float2bfloat16(Wh[i]);
    else if (i < N1 + N2) Wqkb[i - N1] = __float2bfloat16(Wqk[i - N1]);
    else if (i < N1 + N2 + N3) Wob[i - N1 - N2] = __float2bfloat16(Wo[i - N1 - N2]);
}

// 128 threads, float4 loads, bf16x2 packed stores
__global__ void ln_kernel(const float4* __restrict__ x4, const float4* __restrict__ w4,
                          const float4* __restrict__ b4, uint2* __restrict__ out) {
    int tok = blockIdx.x;
    int t = threadIdx.x;
    float4 v = x4[(long)tok * 128 + t];
    float s  = v.x + v.y + v.z + v.w;
    float sq = v.x * v.x + v.y * v.y + v.z * v.z + v.w * v.w;
    #pragma unroll
    for (int o = 16; o; o >>= 1) {
        s  += __shfl_xor_sync(0xffffffffu, s,  o);
        sq += __shfl_xor_sync(0xffffffffu, sq, o);
    }
    __shared__ float ss[4], sv[4];
    if ((t & 31) == 0) { ss[t >> 5] = s; sv[t >> 5] = sq; }
    __syncthreads();
    float S = ss[0] + ss[1] + ss[2] + ss[3];
    float Q = sv[0] + sv[1] + sv[2] + sv[3];
    float mu  = S * (1.0f / DIMC);
    float var = Q * (1.0f / DIMC) - mu * mu;
    float rs  = rsqrtf(var + 1e-5f);
    float4 w = w4[t], b = b4[t];
    float r0 = (v.x - mu) * rs * w.x + b.x;
    float r1 = (v.y - mu) * rs * w.y + b.y;
    float r2 = (v.z - mu) * rs * w.z + b.z;
    float r3 = (v.w - mu) * rs * w.w + b.w;
    uint2 u;
    u.x = packbf(r0, r1);
    u.y = packbf(r2, r3);
    out[(long)tok * 128 + t] = u;
}

// exclusive cumsum over groups (g dim), fp32 in -> bf16 out
__global__ void cumsum_kv(const float* __restrict__ kv, __nv_bfloat16* __restrict__ out) {
    long i = (long)blockIdx.x * 256 + threadIdx.x;
    const long GE = (long)QKC * HIDC;                 // 131072
    if (i >= 4 * GE) return;
    int  bb = (int)(i / GE);
    long e  = i % GE;
    float s = 0.0f;
    #pragma unroll
    for (int g = 0; g < GPB; g++) {
        long o = ((long)(bb * GPB + g)) * GE + e;
        out[o] = __float2bfloat16(s);
        s += kv[o];
    }
}

// ------------------------------- launcher -----------------------------------
extern "C" void kernel_launch(void* const* d_in, const int* in_sizes, int n_in,
                              void* d_out, int out_size) {
    const float* x     = (const float*)d_in[0];
    const float* ln_w  = (const float*)d_in[1];
    const float* ln_b  = (const float*)d_in[2];
    const float* Wh    = (const float*)d_in[3];
    const float* bh    = (const float*)d_in[4];
    const float* Wqk   = (const float*)d_in[5];
    const float* bqk   = (const float*)d_in[6];
    const float* gamma = (const float*)d_in[7];
    const float* beta  = (const float*)d_in[8];
    const float* Wo    = (const float*)d_in[9];
    const float* bo    = (const float*)d_in[10];
    float* out = (float*)d_out;

    __nv_bfloat16 *normed, *Whb, *Wqkb, *Wob, *v, *gate, *qh, *lkT, *S, *linkvc, *outp;
    float *linkv;
    cudaGetSymbolAddress((void**)&normed, g_normed);
    cudaGetSymbolAddress((void**)&Whb,    g_Whb);
    cudaGetSymbolAddress((void**)&Wqkb,   g_Wqkb);
    cudaGetSymbolAddress((void**)&Wob,    g_Wob);
    cudaGetSymbolAddress((void**)&v,      g_v);
    cudaGetSymbolAddress((void**)&gate,   g_gate);
    cudaGetSymbolAddress((void**)&qh,     g_qh);
    cudaGetSymbolAddress((void**)&lkT,    g_lkT);
    cudaGetSymbolAddress((void**)&S,      g_S);
    cudaGetSymbolAddress((void**)&linkv,  g_linkv);
    cudaGetSymbolAddress((void**)&linkvc, g_linkvc);
    cudaGetSymbolAddress((void**)&outp,   g_outp);

    const long HSZ = (long)NTOK * QKC;   // per-head size
    __nv_bfloat16* quad_q = qh;
    __nv_bfloat16* lin_q  = qh + HSZ;
    __nv_bfloat16* quad_k = qh + 2 * HSZ;

    // dynamic smem sizes (3 stages)
    const int SM64_128 = 3 * (128 * 72 + 64 * 136) * 2;   // KT=64, BM=128: 107520
    const int SM64_64  = 3 * (64 * 72  + 64 * 136) * 2;   // KT=64, BM=64:   79872
    const int SM0      = 3 * (128 * 40 + 128 * 40) * 2;   // KT=32, NK:      61440
    cudaFuncSetAttribute((const void*)gemm15<EPI_H,       1, 0, 0, 4, 64>, cudaFuncAttributeMaxDynamicSharedMemorySize, SM64_128);
    cudaFuncSetAttribute((const void*)gemm15<EPI_QK,      1, 0, 0, 2, 64>, cudaFuncAttributeMaxDynamicSharedMemorySize, SM64_64);
    cudaFuncSetAttribute((const void*)gemm15<EPI_RELU2,   0, 0, 0, 4, 32>, cudaFuncAttributeMaxDynamicSharedMemorySize, SM0);
    cudaFuncSetAttribute((const void*)gemm15<EPI_LINKV,   1, 0, 0, 4, 64>, cudaFuncAttributeMaxDynamicSharedMemorySize, SM64_128);
    cudaFuncSetAttribute((const void*)gemm15<EPI_COMBINE, 1, 1, 1, 4, 64>, cudaFuncAttributeMaxDynamicSharedMemorySize, SM64_128);
    cudaFuncSetAttribute((const void*)gemm15<EPI_FINAL,   1, 0, 0, 4, 64>, cudaFuncAttributeMaxDynamicSharedMemorySize, SM64_128);

    // 1. weight converts + layernorm
    const int NCV = DIMC * 2 * HIDC + DIMC * QKC + HIDC * DIMC;
    f2b_all<<<(NCV + 255) / 256, 256>>>(Wh, Wqk, Wo, Whb, Wqkb, Wob);
    ln_kernel<<<NTOK, 128>>>((const float4*)x, (const float4*)ln_w,
                             (const float4*)ln_b, (uint2*)normed);

    // 2. h = silu(normed @ Wh + bh) -> v, gate
    {
        EpiParams p{}; p.bias = bh; p.out_b0 = v; p.out_b1 = gate;
        gemm15<EPI_H, 1, 0, 0, 4, 64><<<dim3(2 * HIDC / 128, NTOK / 128, 1), 256, SM64_128>>>(
            normed, Whb, 0, 0, DIMC, nullptr, nullptr, 0, 0, 0,
            2 * HIDC, DIMC, 0, p);
    }
    // 3. qk heads (M=64 tiles; lin_k written transposed into lkT)
    {
        EpiParams p{}; p.bias = bqk; p.gamma = gamma; p.beta = beta;
        p.out_b0 = quad_q; p.out_b1 = lin_q; p.out_b2 = quad_k; p.out_b3 = lkT;
        gemm15<EPI_QK, 1, 0, 0, 2, 64><<<dim3(1, NTOK / 64, 1), 256, SM64_64>>>(
            normed, Wqkb, 0, 0, DIMC, nullptr, nullptr, 0, 0, 0,
            QKC, DIMC, 0, p);
    }
    // 4. S = relu2(QK^T / G), causal (upper block skipped)
    {
        EpiParams p{}; p.out_b0 = S;
        gemm15<EPI_RELU2, 0, 0, 0, 4, 32><<<dim3(2, 2, NGRP), 256, SM0>>>(
            quad_q, quad_k, (long)GRP * QKC, (long)GRP * QKC, QKC,
            nullptr, nullptr, 0, 0, 0, GRP, QKC, 0, p);
    }
    // 6. linkv = lk^T @ V / G
    {
        EpiParams p{}; p.out_f = linkv;
        gemm15<EPI_LINKV, 1, 0, 0, 4, 64><<<dim3(HIDC / 128, 1, NGRP), 256, SM64_128>>>(
            lkT, v, (long)QKC * GRP, (long)GRP * HIDC, GRP,
            nullptr, nullptr, 0, 0, 0, HIDC, GRP, 0, p);
    }
    // 7. exclusive cumsum over groups
    cumsum_kv<<<(4 * QKC * HIDC / 256), 256>>>(linkv, linkvc);

    // 8. outp = gate * (S@V + lq @ linkvc)    [fused quad + combine]
    {
        EpiParams p{}; p.gate = gate; p.out_b0 = outp;
        gemm15<EPI_COMBINE, 1, 1, 1, 4, 64><<<dim3(HIDC / 128, 2, NGRP), 256, SM64_128>>>(
            S, v, (long)GRP * GRP, (long)GRP * HIDC, GRP,
            lin_q, linkvc, (long)GRP * QKC, (long)QKC * HIDC, QKC,
            HIDC, GRP, QKC, p);
    }
    // 9. out = outp @ Wo + bo + x
    {
        EpiParams p{}; p.bias = bo; p.x = x; p.out_f = out;
        gemm15<EPI_FINAL, 1, 0, 0, 4, 64><<<dim3(DIMC / 128, NTOK / 128, 1), 256, SM64_128>>>(
            outp, Wob, 0, 0, HIDC, nullptr, nullptr, 0, 0, 0,
            DIMC, HIDC, 0, p);
    }
}

// round 17
// speedup vs baseline: 1.2224x; 1.0115x over previous
#include <cuda_runtime.h>
#include <cuda_bf16.h>
#include <cstdint>

// ---------------------------------------------------------------------------
// FLASH / GAU block on GB300 — round 16:
//  * R15 base (382.0 us) + ONE __syncthreads per k-tile (loop reordered:
//    wait/barrier BEFORE prefetch, so the barrier guards slot reuse; wait0 on
//    the final tile since empty commits are gone)
//  * relu2 GEMM moved to KT=64 (generalized NK B-stage layout)
// ---------------------------------------------------------------------------

#define DIMC   512
#define HIDC   1024
#define QKC    128
#define GRP    256
#define NTOK   16384            // 4 * 4096
#define NGRP   64               // 4 * 16
#define GPB    16               // groups per batch

// ------------------------- scratch (device globals) ------------------------
__device__ __nv_bfloat16 g_normed[NTOK * DIMC];
__device__ __nv_bfloat16 g_Whb   [DIMC * 2 * HIDC];
__device__ __nv_bfloat16 g_Wqkb  [DIMC * QKC];
__device__ __nv_bfloat16 g_Wob   [HIDC * DIMC];
__device__ __nv_bfloat16 g_v     [NTOK * HIDC];
__device__ __nv_bfloat16 g_gate  [NTOK * HIDC];
__device__ __nv_bfloat16 g_qh    [3 * NTOK * QKC];      // quad_q, lin_q, quad_k
__device__ __nv_bfloat16 g_lkT   [NGRP * QKC * GRP];    // lin_k, transposed per group
__device__ __nv_bfloat16 g_S     [NGRP * GRP * GRP];
__device__ float         g_linkv [NGRP * QKC * HIDC];
__device__ __nv_bfloat16 g_linkvc[NGRP * QKC * HIDC];
__device__ __nv_bfloat16 g_outp  [NTOK * HIDC];

// ------------------------------ helpers ------------------------------------
__device__ __forceinline__ float silu_f(float v) {
    return v * (1.0f / (1.0f + __expf(-v)));
}

__device__ __forceinline__ uint32_t packbf(float a, float b) {
    __nv_bfloat162 h = __floats2bfloat162_rn(a, b);
    return *(uint32_t*)&h;
}

__device__ __forceinline__ void mma16816(float* c, const uint32_t* a, const uint32_t* b) {
    asm volatile(
        "mma.sync.aligned.m16n8k16.row.col.f32.bf16.bf16.f32 "
        "{%0,%1,%2,%3},{%4,%5,%6,%7},{%8,%9},{%0,%1,%2,%3};\n"
        : "+f"(c[0]), "+f"(c[1]), "+f"(c[2]), "+f"(c[3])
        : "r"(a[0]), "r"(a[1]), "r"(a[2]), "r"(a[3]), "r"(b[0]), "r"(b[1]));
}

__device__ __forceinline__ void cp16(uint32_t dst, const void* src) {
    asm volatile("cp.async.cg.shared.global [%0], [%1], 16;\n" :: "r"(dst), "l"(src));
}
__device__ __forceinline__ void cp_commit() {
    asm volatile("cp.async.commit_group;\n" ::: "memory");
}
__device__ __forceinline__ void cp_wait0() {
    asm volatile("cp.async.wait_group 0;\n" ::: "memory");
}
__device__ __forceinline__ void cp_wait1() {
    asm volatile("cp.async.wait_group 1;\n" ::: "memory");
}

__device__ __forceinline__ void ldsm4(uint32_t* r, uint32_t a) {
    asm volatile("ldmatrix.sync.aligned.m8n8.x4.shared.b16 {%0,%1,%2,%3},[%4];\n"
        : "=r"(r[0]), "=r"(r[1]), "=r"(r[2]), "=r"(r[3]) : "r"(a));
}
__device__ __forceinline__ void ldsm4t(uint32_t* r, uint32_t a) {
    asm volatile("ldmatrix.sync.aligned.m8n8.x4.trans.shared.b16 {%0,%1,%2,%3},[%4];\n"
        : "=r"(r[0]), "=r"(r[1]), "=r"(r[2]), "=r"(r[3]) : "r"(a));
}

struct EpiParams {
    const float* bias;
    const float* x;                 // final residual
    const __nv_bfloat16* gate;
    const float* gamma;
    const float* beta;
    float* out_f;
    __nv_bfloat16* out_b0;
    __nv_bfloat16* out_b1;
    __nv_bfloat16* out_b2;
    __nv_bfloat16* out_b3;          // lkT for EPI_QK
};

#define EPI_H       0
#define EPI_QK      1
#define EPI_RELU2   2
#define EPI_LINKV   4
#define EPI_COMBINE 5
#define EPI_FINAL   6

// packed epilogue: handles the (n, n+1) accumulator pair with wide stores
template<int EPI>
__device__ __forceinline__ void epi_store2(const EpiParams& p, int z, int m, int n,
                                           float a0, float a1) {
    if constexpr (EPI == EPI_H) {
        float v0 = silu_f(a0 + p.bias[n]);
        float v1 = silu_f(a1 + p.bias[n + 1]);
        uint32_t u = packbf(v0, v1);
        if (n < HIDC) *(uint32_t*)(p.out_b0 + (long)m * HIDC + n)        = u;
        else          *(uint32_t*)(p.out_b1 + (long)m * HIDC + n - HIDC) = u;
    } else if constexpr (EPI == EPI_QK) {
        float v0 = silu_f(a0 + p.bias[n]);
        float v1 = silu_f(a1 + p.bias[n + 1]);
        long o = (long)m * QKC + n;
        *(uint32_t*)(p.out_b0 + o) = packbf(v0 * p.gamma[n]           + p.beta[n],
                                            v1 * p.gamma[n + 1]       + p.beta[n + 1]);
        *(uint32_t*)(p.out_b1 + o) = packbf(v0 * p.gamma[QKC + n]     + p.beta[QKC + n],
                                            v1 * p.gamma[QKC + n + 1] + p.beta[QKC + n + 1]);
        *(uint32_t*)(p.out_b2 + o) = packbf(v0 * p.gamma[2 * QKC + n]     + p.beta[2 * QKC + n],
                                            v1 * p.gamma[2 * QKC + n + 1] + p.beta[2 * QKC + n + 1]);
        // lin_k head: store TRANSPOSED into lkT[z][d][t]  (z = m>>8, t = m&255)
        float h3a = v0 * p.gamma[3 * QKC + n]     + p.beta[3 * QKC + n];
        float h3b = v1 * p.gamma[3 * QKC + n + 1] + p.beta[3 * QKC + n + 1];
        __nv_bfloat16* lb = p.out_b3 + (long)(m >> 8) * QKC * GRP + (m & 255);
        lb[(long)n * GRP]       = __float2bfloat16(h3a);
        lb[(long)(n + 1) * GRP] = __float2bfloat16(h3b);
    } else if constexpr (EPI == EPI_RELU2) {
        float s0 = fmaxf(a0 * (1.0f / GRP), 0.0f); s0 *= s0;
        float s1 = fmaxf(a1 * (1.0f / GRP), 0.0f); s1 *= s1;
        if (n > m)     s0 = 0.0f;    // causal within group
        if (n + 1 > m) s1 = 0.0f;
        *(uint32_t*)(p.out_b0 + (long)z * GRP * GRP + m * GRP + n) = packbf(s0, s1);
    } else if constexpr (EPI == EPI_LINKV) {
        float2 r = make_float2(a0 * (1.0f / GRP), a1 * (1.0f / GRP));
        *(float2*)(p.out_f + (long)z * QKC * HIDC + (long)m * HIDC + n) = r;
    } else if constexpr (EPI == EPI_COMBINE) {
        long o = (long)z * GRP * HIDC + (long)m * HIDC + n;
        uint32_t gu = *(const uint32_t*)(p.gate + o);
        __nv_bfloat162 gh = *(__nv_bfloat162*)&gu;
        *(uint32_t*)(p.out_b0 + o) = packbf(__bfloat162float(gh.x) * a0,
                                            __bfloat162float(gh.y) * a1);
    } else { // EPI_FINAL
        long o = (long)m * DIMC + n;
        float2 xr = *(const float2*)(p.x + o);
        float2 r = make_float2(a0 + p.bias[n] + xr.x, a1 + p.bias[n + 1] + xr.y);
        *(float2*)(p.out_f + o) = r;
    }
}

// ---------------------------------------------------------------------------
// 3-stage pipelined bf16 GEMM, ONE __syncthreads per k-tile.
//   C[M,N] = A[M,K1] @ B  (+ A2[M,K2] @ B2 if DUAL)
//   BLAY == 0: B is [N,K] row-major (K-contiguous)   (ldb == K1)
//   BLAY == 1: B is [K,N] row-major (N-contiguous)   (ldb == N)
//   CAUSALA:   trim K1 to (bm+1)*BM (S@V pair: S lower-triangular)
//   MT: m-tiles per warp (4 -> BM=128, 2 -> BM=64);  KT: k-tile (32/64)
// Loop order {wait; barrier; prefetch(gt+2); compute} makes the top barrier
// guard slot reuse (slot (gt+2)%3 == slot read at gt-1). Final tile uses
// wait0 (no empty commits inflate the group count).
// Block tile BMx128, 256 threads, 8 warps 2(M)x4(N).
// ---------------------------------------------------------------------------
template<int EPI, int BLAY, int CAUSALA, int DUAL, int MT, int KT>
__global__ __launch_bounds__(256) void gemm16(
    const __nv_bfloat16* __restrict__ A,  const __nv_bfloat16* __restrict__ B,
    long sAz, long sBz, int lda1,
    const __nv_bfloat16* __restrict__ A2, const __nv_bfloat16* __restrict__ B2,
    long sA2z, long sB2z, int lda2,
    int N, int K1, int K2, EpiParams p)
{
    constexpr int BM  = 32 * MT;                            // 128 or 64
    constexpr int AST = KT + 8;                             // smem row stride (K-contig)
    constexpr int SAE = BM * AST;                           // A stage elems
    constexpr int SBE = (BLAY == 1) ? KT * 136 : 128 * AST; // B stage elems
    extern __shared__ __nv_bfloat16 dsm[];

    const int z  = blockIdx.z;
    const int bm = blockIdx.y;
    const int bn = blockIdx.x;
    if constexpr (EPI == EPI_RELU2) { if (bn > bm) return; }   // fully masked tile

    const __nv_bfloat16* A1b = A  + (long)z * sAz;
    const __nv_bfloat16* B1b = B  + (long)z * sBz;
    const __nv_bfloat16* A2b = DUAL ? (A2 + (long)z * sA2z) : nullptr;
    const __nv_bfloat16* B2b = DUAL ? (B2 + (long)z * sB2z) : nullptr;

    const int t    = threadIdx.x;
    const int wid  = t >> 5;
    const int lane = t & 31;
    const int wm   = wid & 1;        // 0..1  (BM/2 rows each)
    const int wn   = wid >> 1;       // 0..3  (32 cols each)
    const int gID  = lane >> 2;      // 0..7
    const int tg   = lane & 3;       // 0..3

    const int Keff1 = CAUSALA ? ((bm + 1) * BM < K1 ? (bm + 1) * BM : K1) : K1;
    const int nk1 = Keff1 / KT;
    const int nk2 = DUAL ? (K2 / KT) : 0;
    const int nt  = nk1 + nk2;

    const uint32_t sAu = (uint32_t)__cvta_generic_to_shared(dsm);
    const uint32_t sBu = sAu + 3 * SAE * 2;

    float acc[MT][4][4];
    #pragma unroll
    for (int i = 0; i < MT; i++)
        #pragma unroll
        for (int j = 0; j < 4; j++)
            #pragma unroll
            for (int r = 0; r < 4; r++) acc[i][j][r] = 0.0f;

    // ---- stage loader (all cp.async) ----
    auto load_stage = [&](int st, int gt) {
        const __nv_bfloat16* Ab;
        const __nv_bfloat16* Bb;
        int lda, k0;
        if (!DUAL || gt < nk1) { Ab = A1b; Bb = B1b; lda = lda1; k0 = gt * KT; }
        else                   { Ab = A2b; Bb = B2b; lda = lda2; k0 = (gt - nk1) * KT; }
        {   // A tile: [BM rows, KT k] -> sA[st][row*AST + k]
            constexpr int TPR = KT / 8;          // threads per A row
            constexpr int RPP = 256 / TPR;       // rows per pass
            int r = t / TPR, c = (t % TPR) * 8;
            #pragma unroll
            for (int rr = 0; rr < BM; rr += RPP) {
                uint32_t d = sAu + (uint32_t)(st * SAE + (r + rr) * AST + c) * 2;
                cp16(d, Ab + (long)(bm * BM + r + rr) * lda + k0 + c);
            }
        }
        if (BLAY == 0) {   // B [N,K]: sB[st][n*AST + k]  (ldb == K1)
            constexpr int TPR = KT / 8;
            constexpr int RPP = 256 / TPR;
            int r = t / TPR, c = (t % TPR) * 8;
            #pragma unroll
            for (int rr = 0; rr < 128; rr += RPP) {
                uint32_t d = sBu + (uint32_t)(st * SBE + (r + rr) * AST + c) * 2;
                cp16(d, Bb + (long)(bn * 128 + r + rr) * K1 + k0 + c);
            }
        } else {           // B [K,N]: sB[st][k*136 + n]  (ldb == N)
            int r = t >> 4, c = (t & 15) * 8;
            #pragma unroll
            for (int rr = 0; rr < KT; rr += 16) {
                uint32_t d = sBu + (uint32_t)(st * SBE + (r + rr) * 136 + c) * 2;
                cp16(d, Bb + (long)(k0 + r + rr) * N + bn * 128 + c);
            }
        }
    };

    // prologue: stages 0 and 1 (all call sites have nt >= 2)
    load_stage(0, 0); cp_commit();
    load_stage(1, 1); cp_commit();

    for (int gt = 0; gt < nt; gt++) {
        if (gt == nt - 1) cp_wait0(); else cp_wait1();
        __syncthreads();
        if (gt + 2 < nt) { load_stage((gt + 2) % 3, gt + 2); cp_commit(); }

        const int st = gt % 3;
        const uint32_t aB = sAu + (uint32_t)(st * SAE) * 2;
        const uint32_t bB = sBu + (uint32_t)(st * SBE) * 2;

        #pragma unroll
        for (int kk = 0; kk < KT; kk += 16) {
            uint32_t af[MT][4];
            #pragma unroll
            for (int mt = 0; mt < MT; mt++) {
                uint32_t a = aB + (uint32_t)((wm * (BM / 2) + mt * 16 + (lane & 15)) * AST
                                             + kk + ((lane >> 4) * 8)) * 2;
                ldsm4(af[mt], a);
            }
            uint32_t bfr[2][4];
            #pragma unroll
            for (int h = 0; h < 2; h++) {
                int n0 = wn * 32 + h * 16;
                if (BLAY == 0) {
                    uint32_t a = bB + (uint32_t)((n0 + (lane & 7) + ((lane >> 4) << 3)) * AST
                                                 + kk + (((lane >> 3) & 1) * 8)) * 2;
                    ldsm4(bfr[h], a);
                } else {
                    uint32_t a = bB + (uint32_t)((kk + (lane & 15)) * 136
                                                 + n0 + ((lane >> 4) * 8)) * 2;
                    ldsm4t(bfr[h], a);
                }
            }
            #pragma unroll
            for (int mt = 0; mt < MT; mt++)
                #pragma unroll
                for (int j = 0; j < 4; j++) {
                    uint32_t bb[2] = { bfr[j >> 1][(j & 1) * 2],
                                       bfr[j >> 1][(j & 1) * 2 + 1] };
                    mma16816(acc[mt][j], af[mt], bb);
                }
        }
    }

    #pragma unroll
    for (int mt = 0; mt < MT; mt++)
        #pragma unroll
        for (int j = 0; j < 4; j++) {
            int m0 = bm * BM + wm * (BM / 2) + mt * 16 + gID;
            int n0 = bn * 128 + wn * 32 + j * 8 + tg * 2;
            epi_store2<EPI>(p, z, m0,     n0, acc[mt][j][0], acc[mt][j][1]);
            epi_store2<EPI>(p, z, m0 + 8, n0, acc[mt][j][2], acc[mt][j][3]);
        }
}

// ----------------------------- small kernels --------------------------------
// single kernel converting all three weight matrices fp32 -> bf16
__global__ void f2b_all(const float* __restrict__ Wh, const float* __restrict__ Wqk,
                        const float* __restrict__ Wo,
                        __nv_bfloat16* __restrict__ Whb, __nv_bfloat16* __restrict__ Wqkb,
                        __nv_bfloat16* __restrict__ Wob) {
    const int N1 = DIMC * 2 * HIDC;          // 1048576
    const int N2 = DIMC * QKC;               // 65536
    const int N3 = HIDC * DIMC;              // 524288
    int i = blockIdx.x * 256 + threadIdx.x;
    if (i < N1) Whb[i] = __float2bfloat16(Wh[i]);
    else if (i < N1 + N2) Wqkb[i - N1] = __float2bfloat16(Wqk[i - N1]);
    else if (i < N1 + N2 + N3) Wob[i - N1 - N2] = __float2bfloat16(Wo[i - N1 - N2]);
}

// 128 threads, float4 loads, bf16x2 packed stores
__global__ void ln_kernel(const float4* __restrict__ x4, const float4* __restrict__ w4,
                          const float4* __restrict__ b4, uint2* __restrict__ out) {
    int tok = blockIdx.x;
    int t = threadIdx.x;
    float4 v = x4[(long)tok * 128 + t];
    float s  = v.x + v.y + v.z + v.w;
    float sq = v.x * v.x + v.y * v.y + v.z * v.z + v.w * v.w;
    #pragma unroll
    for (int o = 16; o; o >>= 1) {
        s  += __shfl_xor_sync(0xffffffffu, s,  o);
        sq += __shfl_xor_sync(0xffffffffu, sq, o);
    }
    __shared__ float ss[4], sv[4];
    if ((t & 31) == 0) { ss[t >> 5] = s; sv[t >> 5] = sq; }
    __syncthreads();
    float S = ss[0] + ss[1] + ss[2] + ss[3];
    float Q = sv[0] + sv[1] + sv[2] + sv[3];
    float mu  = S * (1.0f / DIMC);
    float var = Q * (1.0f / DIMC) - mu * mu;
    float rs  = rsqrtf(var + 1e-5f);
    float4 w = w4[t], b = b4[t];
    float r0 = (v.x - mu) * rs * w.x + b.x;
    float r1 = (v.y - mu) * rs * w.y + b.y;
    float r2 = (v.z - mu) * rs * w.z + b.z;
    float r3 = (v.w - mu) * rs * w.w + b.w;
    uint2 u;
    u.x = packbf(r0, r1);
    u.y = packbf(r2, r3);
    out[(long)tok * 128 + t] = u;
}

// exclusive cumsum over groups (g dim), fp32 in -> bf16 out
__global__ void cumsum_kv(const float* __restrict__ kv, __nv_bfloat16* __restrict__ out) {
    long i = (long)blockIdx.x * 256 + threadIdx.x;
    const long GE = (long)QKC * HIDC;                 // 131072
    if (i >= 4 * GE) return;
    int  bb = (int)(i / GE);
    long e  = i % GE;
    float s = 0.0f;
    #pragma unroll
    for (int g = 0; g < GPB; g++) {
        long o = ((long)(bb * GPB + g)) * GE + e;
        out[o] = __float2bfloat16(s);
        s += kv[o];
    }
}

// ------------------------------- launcher -----------------------------------
extern "C" void kernel_launch(void* const* d_in, const int* in_sizes, int n_in,
                              void* d_out, int out_size) {
    const float* x     = (const float*)d_in[0];
    const float* ln_w  = (const float*)d_in[1];
    const float* ln_b  = (const float*)d_in[2];
    const float* Wh    = (const float*)d_in[3];
    const float* bh    = (const float*)d_in[4];
    const float* Wqk   = (const float*)d_in[5];
    const float* bqk   = (const float*)d_in[6];
    const float* gamma = (const float*)d_in[7];
    const float* beta  = (const float*)d_in[8];
    const float* Wo    = (const float*)d_in[9];
    const float* bo    = (const float*)d_in[10];
    float* out = (float*)d_out;

    __nv_bfloat16 *normed, *Whb, *Wqkb, *Wob, *v, *gate, *qh, *lkT, *S, *linkvc, *outp;
    float *linkv;
    cudaGetSymbolAddress((void**)&normed, g_normed);
    cudaGetSymbolAddress((void**)&Whb,    g_Whb);
    cudaGetSymbolAddress((void**)&Wqkb,   g_Wqkb);
    cudaGetSymbolAddress((void**)&Wob,    g_Wob);
    cudaGetSymbolAddress((void**)&v,      g_v);
    cudaGetSymbolAddress((void**)&gate,   g_gate);
    cudaGetSymbolAddress((void**)&qh,     g_qh);
    cudaGetSymbolAddress((void**)&lkT,    g_lkT);
    cudaGetSymbolAddress((void**)&S,      g_S);
    cudaGetSymbolAddress((void**)&linkv,  g_linkv);
    cudaGetSymbolAddress((void**)&linkvc, g_linkvc);
    cudaGetSymbolAddress((void**)&outp,   g_outp);

    const long HSZ = (long)NTOK * QKC;   // per-head size
    __nv_bfloat16* quad_q = qh;
    __nv_bfloat16* lin_q  = qh + HSZ;
    __nv_bfloat16* quad_k = qh + 2 * HSZ;

    // dynamic smem sizes (3 stages)
    const int SM64_128 = 3 * (128 * 72 + 64 * 136) * 2;   // KT=64 KN, BM=128: 107520
    const int SM64_64  = 3 * (64 * 72  + 64 * 136) * 2;   // KT=64 KN, BM=64:   79872
    const int SM0_64   = 3 * (128 * 72 + 128 * 72) * 2;   // KT=64 NK:         110592
    cudaFuncSetAttribute((const void*)gemm16<EPI_H,       1, 0, 0, 4, 64>, cudaFuncAttributeMaxDynamicSharedMemorySize, SM64_128);
    cudaFuncSetAttribute((const void*)gemm16<EPI_QK,      1, 0, 0, 2, 64>, cudaFuncAttributeMaxDynamicSharedMemorySize, SM64_64);
    cudaFuncSetAttribute((const void*)gemm16<EPI_RELU2,   0, 0, 0, 4, 64>, cudaFuncAttributeMaxDynamicSharedMemorySize, SM0_64);
    cudaFuncSetAttribute((const void*)gemm16<EPI_LINKV,   1, 0, 0, 4, 64>, cudaFuncAttributeMaxDynamicSharedMemorySize, SM64_128);
    cudaFuncSetAttribute((const void*)gemm16<EPI_COMBINE, 1, 1, 1, 4, 64>, cudaFuncAttributeMaxDynamicSharedMemorySize, SM64_128);
    cudaFuncSetAttribute((const void*)gemm16<EPI_FINAL,   1, 0, 0, 4, 64>, cudaFuncAttributeMaxDynamicSharedMemorySize, SM64_128);

    // 1. weight converts + layernorm
    const int NCV = DIMC * 2 * HIDC + DIMC * QKC + HIDC * DIMC;
    f2b_all<<<(NCV + 255) / 256, 256>>>(Wh, Wqk, Wo, Whb, Wqkb, Wob);
    ln_kernel<<<NTOK, 128>>>((const float4*)x, (const float4*)ln_w,
                             (const float4*)ln_b, (uint2*)normed);

    // 2. h = silu(normed @ Wh + bh) -> v, gate
    {
        EpiParams p{}; p.bias = bh; p.out_b0 = v; p.out_b1 = gate;
        gemm16<EPI_H, 1, 0, 0, 4, 64><<<dim3(2 * HIDC / 128, NTOK / 128, 1), 256, SM64_128>>>(
            normed, Whb, 0, 0, DIMC, nullptr, nullptr, 0, 0, 0,
            2 * HIDC, DIMC, 0, p);
    }
    // 3. qk heads (M=64 tiles; lin_k written transposed into lkT)
    {
        EpiParams p{}; p.bias = bqk; p.gamma = gamma; p.beta = beta;
        p.out_b0 = quad_q; p.out_b1 = lin_q; p.out_b2 = quad_k; p.out_b3 = lkT;
        gemm16<EPI_QK, 1, 0, 0, 2, 64><<<dim3(1, NTOK / 64, 1), 256, SM64_64>>>(
            normed, Wqkb, 0, 0, DIMC, nullptr, nullptr, 0, 0, 0,
            QKC, DIMC, 0, p);
    }
    // 4. S = relu2(QK^T / G), causal (upper block skipped)
    {
        EpiParams p{}; p.out_b0 = S;
        gemm16<EPI_RELU2, 0, 0, 0, 4, 64><<<dim3(2, 2, NGRP), 256, SM0_64>>>(
            quad_q, quad_k, (long)GRP * QKC, (long)GRP * QKC, QKC,
            nullptr, nullptr, 0, 0, 0, GRP, QKC, 0, p);
    }
    // 6. linkv = lk^T @ V / G
    {
        EpiParams p{}; p.out_f = linkv;
        gemm16<EPI_LINKV, 1, 0, 0, 4, 64><<<dim3(HIDC / 128, 1, NGRP), 256, SM64_128>>>(
            lkT, v, (long)QKC * GRP, (long)GRP * HIDC, GRP,
            nullptr, nullptr, 0, 0, 0, HIDC, GRP, 0, p);
    }
    // 7. exclusive cumsum over groups
    cumsum_kv<<<(4 * QKC * HIDC / 256), 256>>>(linkv, linkvc);

    // 8. outp = gate * (S@V + lq @ linkvc)    [fused quad + combine]
    {
        EpiParams p{}; p.gate = gate; p.out_b0 = outp;
        gemm16<EPI_COMBINE, 1, 1, 1, 4, 64><<<dim3(HIDC / 128, 2, NGRP), 256, SM64_128>>>(
            S, v, (long)GRP * GRP, (long)GRP * HIDC, GRP,
            lin_q, linkvc, (long)GRP * QKC, (long)QKC * HIDC, QKC,
            HIDC, GRP, QKC, p);
    }
    // 9. out = outp @ Wo + bo + x
    {
        EpiParams p{}; p.bias = bo; p.x = x; p.out_f = out;
        gemm16<EPI_FINAL, 1, 0, 0, 4, 64><<<dim3(DIMC / 128, NTOK / 128, 1), 256, SM64_128>>>(
            outp, Wob, 0, 0, HIDC, nullptr, nullptr, 0, 0, 0,
            DIMC, HIDC, 0, p);
    }
}